// round 10
// baseline (speedup 1.0000x reference)
#include <cuda_runtime.h>
#include <cstdint>
#include <cstddef>

// ---------------------------------------------------------------------------
// GATEncoder: GATConv(2000->4x512, mean heads) -> BN -> ELU -> GATConv(512->30)
// N=50000, F=2000, H=4, C=512, LAT=30, E=800000 (+N self loops)
// R9: R7 retry with the host-side device-symbol-as-arg bug fixed:
//     k_gemm1 references g_Art/g_W1r directly (no device symbols passed from
//     host). Pre-rounded tf32 operands, BM=256xBN=128, 6-stage cp.async.
// ---------------------------------------------------------------------------

#define NMAX 50000
#define EMAX 800000
#define ETMAX (EMAX + NMAX)
#define GEMM_STAGES 6
#define AS_STRIDE 20
#define BS_STRIDE 136
#define AS_TILE (256 * AS_STRIDE)
#define BS_TILE (16 * BS_STRIDE)
#define SMEM_GEMM (GEMM_STAGES * (AS_TILE + BS_TILE) * 4)   // 175104 B

// ---- device scratch (static; no runtime allocation allowed) ----
__device__ float    g_H1[(size_t)NMAX * 2048];    // x @ W1
__device__ float    g_Art[(size_t)NMAX * 2000];   // tf32-rounded x
__device__ float    g_W1r[(size_t)2000 * 2048];   // tf32-rounded W1
__device__ float    g_out1[(size_t)NMAX * 512];   // layer-1 aggregate
__device__ float    g_hmid[(size_t)NMAX * 512];   // after BN+ELU
__device__ float    g_H2[(size_t)NMAX * 30];      // hmid @ W2
__device__ float    g_asrc1[NMAX * 4];
__device__ float    g_adst1[NMAX * 4];
__device__ float    g_asrc2[NMAX];
__device__ float    g_adst2[NMAX];
__device__ unsigned g_max2[NMAX];
__device__ float    g_sum2[NMAX];
__device__ float    g_e2[ETMAX];
__device__ float    g_stats[1024];                // [0:512) sum, [512:1024) sumsq
// CSR by destination
__device__ int      g_deg[NMAX];
__device__ int      g_rowptr[NMAX + 1];
__device__ int      g_woff[NMAX];
__device__ int      g_csr_src[ETMAX];

// ---- helpers ----
__device__ __forceinline__ float tf32_rne(float x) {
    float r; asm("cvt.rna.tf32.f32 %0, %1;" : "=f"(r) : "f"(x)); return r;
}
__device__ __forceinline__ unsigned f2ord(float f) {
    unsigned u = __float_as_uint(f);
    return (u & 0x80000000u) ? ~u : (u | 0x80000000u);
}
__device__ __forceinline__ float ord2f(unsigned u) {
    unsigned b = (u & 0x80000000u) ? (u & 0x7FFFFFFFu) : ~u;
    return __uint_as_float(b);
}
__device__ __forceinline__ float lrelu(float v) { return v > 0.f ? v : 0.2f * v; }

__device__ __forceinline__ void cp16(void* sptr, const void* gptr, bool pred) {
    unsigned saddr = (unsigned)__cvta_generic_to_shared(sptr);
    int sz = pred ? 16 : 0;
    asm volatile("cp.async.cg.shared.global [%0], [%1], 16, %2;\n"
                 :: "r"(saddr), "l"(gptr), "r"(sz));
}
__device__ __forceinline__ void cp_commit() {
    asm volatile("cp.async.commit_group;\n" ::: "memory");
}
__device__ __forceinline__ void cp_waitg() {
    asm volatile("cp.async.wait_group %0;\n" :: "n"(GEMM_STAGES - 2) : "memory");
}

// ---------------------------------------------------------------------------
// init
// ---------------------------------------------------------------------------
__global__ void k_init(float* __restrict__ out, const float* __restrict__ b2, int Nn) {
    size_t total = (size_t)Nn * 30;
    for (size_t i = (size_t)blockIdx.x * blockDim.x + threadIdx.x; i < total;
         i += (size_t)gridDim.x * blockDim.x) {
        if (i < (size_t)Nn) { g_deg[i] = 0; g_sum2[i] = 0.f; g_max2[i] = 0u; }
        if (i < 1024) g_stats[i] = 0.f;
        out[i] = b2[i % 30];
    }
}

// ---------------------------------------------------------------------------
// pre-round operands to tf32 (RNE) once; removes all cvt from the GEMM loop
// ---------------------------------------------------------------------------
__global__ void k_roundA(const float* __restrict__ x, size_t n4) {
    const float4* src = (const float4*)x;
    float4* dst = (float4*)g_Art;
    for (size_t i = (size_t)blockIdx.x * blockDim.x + threadIdx.x; i < n4;
         i += (size_t)gridDim.x * blockDim.x) {
        float4 v = __ldg(src + i);
        dst[i] = make_float4(tf32_rne(v.x), tf32_rne(v.y), tf32_rne(v.z), tf32_rne(v.w));
    }
}
__global__ void k_roundB(const float* __restrict__ W1, size_t n4) {
    const float4* src = (const float4*)W1;
    float4* dst = (float4*)g_W1r;
    for (size_t i = (size_t)blockIdx.x * blockDim.x + threadIdx.x; i < n4;
         i += (size_t)gridDim.x * blockDim.x) {
        float4 v = __ldg(src + i);
        dst[i] = make_float4(tf32_rne(v.x), tf32_rne(v.y), tf32_rne(v.z), tf32_rne(v.w));
    }
}

// ---------------------------------------------------------------------------
// CSR build: degree count -> exclusive scan -> scatter (src indices)
// ---------------------------------------------------------------------------
__global__ void k_deg(const int* __restrict__ ei, int E, int Nn) {
    int e = blockIdx.x * blockDim.x + threadIdx.x;
    if (e >= E + Nn) return;
    int d = (e < E) ? ei[E + e] : e - E;
    atomicAdd(&g_deg[d], 1);
}

__global__ void k_scan(int Nn) {
    __shared__ int wsum[32];
    __shared__ int carry_s;
    int tid = threadIdx.x;
    if (tid == 0) carry_s = 0;
    __syncthreads();
    int iters = (Nn + 1023) / 1024;
    for (int it = 0; it < iters; it++) {
        int i = it * 1024 + tid;
        int v = (i < Nn) ? g_deg[i] : 0;
        int x = v;
#pragma unroll
        for (int o = 1; o < 32; o <<= 1) {
            int y = __shfl_up_sync(0xffffffffu, x, o);
            if ((tid & 31) >= o) x += y;
        }
        if ((tid & 31) == 31) wsum[tid >> 5] = x;
        __syncthreads();
        if (tid < 32) {
            int w = wsum[tid];
#pragma unroll
            for (int o = 1; o < 32; o <<= 1) {
                int y = __shfl_up_sync(0xffffffffu, w, o);
                if (tid >= o) w += y;
            }
            wsum[tid] = w;
        }
        __syncthreads();
        int warp = tid >> 5;
        int incl = x + (warp ? wsum[warp - 1] : 0);
        int excl = incl - v;
        int c = carry_s;
        if (i < Nn) { g_rowptr[i] = c + excl; g_woff[i] = c + excl; }
        __syncthreads();
        if (tid == 1023) carry_s = c + incl;
        __syncthreads();
    }
    if (tid == 0) g_rowptr[Nn] = carry_s;
}

__global__ void k_scatter(const int* __restrict__ ei, int E, int Nn) {
    int e = blockIdx.x * blockDim.x + threadIdx.x;
    if (e >= E + Nn) return;
    int s, d;
    if (e < E) { s = ei[e]; d = ei[E + e]; } else { s = d = e - E; }
    int pos = atomicAdd(&g_woff[d], 1);
    g_csr_src[pos] = s;
}

// ---------------------------------------------------------------------------
// GEMM1: g_H1[M,2048] = g_Art[M,2000] @ g_W1r[2000,2048], tf32 mma.m16n8k8
// BM=256 BN=128 BK=16, 256 thr = 8 warps (4m x 2n), warp tile 64x64,
// 6-stage cp.async pipeline. Operands referenced via device globals
// (passing __device__ symbols as host-side kernel args is invalid).
// ---------------------------------------------------------------------------
__global__ __launch_bounds__(256, 1)
void k_gemm1(int M) {
    extern __shared__ float smem[];
    float* AsBase = smem;                                // [S][256*20]
    float* BsBase = smem + GEMM_STAGES * AS_TILE;        // [S][16*136]
    const float* A = g_Art;
    const float* B = g_W1r;

    const int tid  = threadIdx.x;
    const int lane = tid & 31, warp = tid >> 5;
    const int gid  = lane >> 2, tig = lane & 3;
    const int wm   = warp >> 1, wn = warp & 1;
    const int rowBase = blockIdx.y * 256;
    const int colBase = blockIdx.x * 128;
    const int KITERS = 125;   // 2000 / 16

    float acc[4][8][4];
#pragma unroll
    for (int i = 0; i < 4; i++)
#pragma unroll
        for (int j = 0; j < 8; j++)
#pragma unroll
            for (int k = 0; k < 4; k++) acc[i][j][k] = 0.f;

    auto load_tile = [&](int st, int k0) {
        float* As = AsBase + st * AS_TILE;
        float* Bs = BsBase + st * BS_TILE;
#pragma unroll
        for (int i = 0; i < 4; i++) {                    // A: 256 rows x 16
            int idx = tid + i * 256;
            int r = idx >> 2;
            int cg = (idx & 3) * 4;
            int gr = rowBase + r;
            cp16(&As[r * AS_STRIDE + cg], A + (size_t)gr * 2000 + k0 + cg, gr < M);
        }
#pragma unroll
        for (int i = 0; i < 2; i++) {                    // B: 16 x 128
            int idx = tid + i * 256;
            int r = idx >> 5;
            int cg = (idx & 31) * 4;
            cp16(&Bs[r * BS_STRIDE + cg], B + (size_t)(k0 + r) * 2048 + colBase + cg, true);
        }
    };

#pragma unroll
    for (int s = 0; s < GEMM_STAGES - 1; s++) {
        load_tile(s, s * 16);
        cp_commit();
    }

    for (int it = 0; it < KITERS; it++) {
        cp_waitg();
        __syncthreads();
        int st = it % GEMM_STAGES;
        float* As = AsBase + st * AS_TILE;
        float* Bs = BsBase + st * BS_TILE;
#pragma unroll
        for (int ks = 0; ks < 2; ks++) {
            unsigned a[4][4], b[8][2];
#pragma unroll
            for (int tm = 0; tm < 4; tm++) {
                int r = wm * 64 + tm * 16;
                int kk = ks * 8 + tig;
                a[tm][0] = __float_as_uint(As[(r + gid) * AS_STRIDE + kk]);
                a[tm][1] = __float_as_uint(As[(r + gid + 8) * AS_STRIDE + kk]);
                a[tm][2] = __float_as_uint(As[(r + gid) * AS_STRIDE + kk + 4]);
                a[tm][3] = __float_as_uint(As[(r + gid + 8) * AS_STRIDE + kk + 4]);
            }
#pragma unroll
            for (int tn = 0; tn < 8; tn++) {
                int c = wn * 64 + tn * 8 + gid;
                b[tn][0] = __float_as_uint(Bs[(ks * 8 + tig) * BS_STRIDE + c]);
                b[tn][1] = __float_as_uint(Bs[(ks * 8 + tig + 4) * BS_STRIDE + c]);
            }
#pragma unroll
            for (int tm = 0; tm < 4; tm++)
#pragma unroll
                for (int tn = 0; tn < 8; tn++) {
                    asm volatile(
                        "mma.sync.aligned.m16n8k8.row.col.f32.tf32.tf32.f32 "
                        "{%0,%1,%2,%3},{%4,%5,%6,%7},{%8,%9},{%0,%1,%2,%3};\n"
                        : "+f"(acc[tm][tn][0]), "+f"(acc[tm][tn][1]),
                          "+f"(acc[tm][tn][2]), "+f"(acc[tm][tn][3])
                        : "r"(a[tm][0]), "r"(a[tm][1]), "r"(a[tm][2]), "r"(a[tm][3]),
                          "r"(b[tn][0]), "r"(b[tn][1]));
                }
        }
        int nit = it + GEMM_STAGES - 1;
        if (nit < KITERS) load_tile(nit % GEMM_STAGES, nit * 16);
        cp_commit();
    }

    // epilogue
#pragma unroll
    for (int tm = 0; tm < 4; tm++) {
        int r0 = rowBase + wm * 64 + tm * 16 + gid;
#pragma unroll
        for (int tn = 0; tn < 8; tn++) {
            int c = colBase + wn * 64 + tn * 8 + tig * 2;
            if (r0 < M) {
                g_H1[(size_t)r0 * 2048 + c]     = acc[tm][tn][0];
                g_H1[(size_t)r0 * 2048 + c + 1] = acc[tm][tn][1];
            }
            if (r0 + 8 < M) {
                g_H1[(size_t)(r0 + 8) * 2048 + c]     = acc[tm][tn][2];
                g_H1[(size_t)(r0 + 8) * 2048 + c + 1] = acc[tm][tn][3];
            }
        }
    }
}

// ---------------------------------------------------------------------------
// attention dots layer 1: a_src/a_dst[n,h] = <H1[n,h,:], att[h,:]>
// ---------------------------------------------------------------------------
__global__ void k_att1(const float* __restrict__ att_src, const float* __restrict__ att_dst,
                       int Nn) {
    int gw = (int)(((size_t)blockIdx.x * blockDim.x + threadIdx.x) >> 5);
    int lane = threadIdx.x & 31;
    if (gw >= Nn * 4) return;
    int n = gw >> 2, h = gw & 3;
    const float4* r4 = (const float4*)(g_H1 + (size_t)n * 2048 + h * 512);
    const float4* s4 = (const float4*)(att_src + h * 512);
    const float4* d4 = (const float4*)(att_dst + h * 512);
    float ss = 0.f, dd = 0.f;
#pragma unroll 4
    for (int i = lane; i < 128; i += 32) {
        float4 v = r4[i], a = s4[i], b = d4[i];
        ss += v.x * a.x + v.y * a.y + v.z * a.z + v.w * a.w;
        dd += v.x * b.x + v.y * b.y + v.z * b.z + v.w * b.w;
    }
#pragma unroll
    for (int off = 16; off; off >>= 1) {
        ss += __shfl_down_sync(0xffffffffu, ss, off);
        dd += __shfl_down_sync(0xffffffffu, dd, off);
    }
    if (lane == 0) { g_asrc1[gw] = ss; g_adst1[gw] = dd; }
}

// ---------------------------------------------------------------------------
// fused layer-1 softmax + aggregation: one block (256 thr) per destination.
// ---------------------------------------------------------------------------
__global__ __launch_bounds__(256)
void k_agg1(int Nn) {
    const int d = blockIdx.x;
    const int tid = threadIdx.x, lane = tid & 31, warp = tid >> 5;
    const int beg = g_rowptr[d], end = g_rowptr[d + 1];

    __shared__ float4 rwarp[8];
    __shared__ float4 rbc;
    __shared__ int    ssrc[256];
    __shared__ float4 sal[256];

    float4 ad = *(const float4*)(g_adst1 + (size_t)d * 4);
    const float NEGINF = __int_as_float(0xff800000);

    float4 mx = make_float4(NEGINF, NEGINF, NEGINF, NEGINF);
    for (int j = beg + tid; j < end; j += 256) {
        int s = g_csr_src[j];
        float4 as = *(const float4*)(g_asrc1 + (size_t)s * 4);
        mx.x = fmaxf(mx.x, lrelu(as.x + ad.x));
        mx.y = fmaxf(mx.y, lrelu(as.y + ad.y));
        mx.z = fmaxf(mx.z, lrelu(as.z + ad.z));
        mx.w = fmaxf(mx.w, lrelu(as.w + ad.w));
    }
#pragma unroll
    for (int o = 16; o; o >>= 1) {
        mx.x = fmaxf(mx.x, __shfl_down_sync(0xffffffffu, mx.x, o));
        mx.y = fmaxf(mx.y, __shfl_down_sync(0xffffffffu, mx.y, o));
        mx.z = fmaxf(mx.z, __shfl_down_sync(0xffffffffu, mx.z, o));
        mx.w = fmaxf(mx.w, __shfl_down_sync(0xffffffffu, mx.w, o));
    }
    if (lane == 0) rwarp[warp] = mx;
    __syncthreads();
    if (tid == 0) {
        float4 m = rwarp[0];
#pragma unroll
        for (int w = 1; w < 8; w++) {
            m.x = fmaxf(m.x, rwarp[w].x); m.y = fmaxf(m.y, rwarp[w].y);
            m.z = fmaxf(m.z, rwarp[w].z); m.w = fmaxf(m.w, rwarp[w].w);
        }
        rbc = m;
    }
    __syncthreads();
    mx = rbc;

    float4 sm = make_float4(0.f, 0.f, 0.f, 0.f);
    for (int j = beg + tid; j < end; j += 256) {
        int s = g_csr_src[j];
        float4 as = *(const float4*)(g_asrc1 + (size_t)s * 4);
        sm.x += expf(lrelu(as.x + ad.x) - mx.x);
        sm.y += expf(lrelu(as.y + ad.y) - mx.y);
        sm.z += expf(lrelu(as.z + ad.z) - mx.z);
        sm.w += expf(lrelu(as.w + ad.w) - mx.w);
    }
#pragma unroll
    for (int o = 16; o; o >>= 1) {
        sm.x += __shfl_down_sync(0xffffffffu, sm.x, o);
        sm.y += __shfl_down_sync(0xffffffffu, sm.y, o);
        sm.z += __shfl_down_sync(0xffffffffu, sm.z, o);
        sm.w += __shfl_down_sync(0xffffffffu, sm.w, o);
    }
    if (lane == 0) rwarp[warp] = sm;
    __syncthreads();
    if (tid == 0) {
        float4 t = rwarp[0];
#pragma unroll
        for (int w = 1; w < 8; w++) {
            t.x += rwarp[w].x; t.y += rwarp[w].y; t.z += rwarp[w].z; t.w += rwarp[w].w;
        }
        rbc = t;
    }
    __syncthreads();
    sm = rbc;
    float4 inv;
    inv.x = 0.25f / (sm.x + 1e-16f);
    inv.y = 0.25f / (sm.y + 1e-16f);
    inv.z = 0.25f / (sm.z + 1e-16f);
    inv.w = 0.25f / (sm.w + 1e-16f);

    float2 acc = make_float2(0.f, 0.f);
    for (int c0 = beg; c0 < end; c0 += 256) {
        int cnt = min(end - c0, 256);
        __syncthreads();
        if (tid < cnt) {
            int s = g_csr_src[c0 + tid];
            float4 as = *(const float4*)(g_asrc1 + (size_t)s * 4);
            float4 al;
            al.x = expf(lrelu(as.x + ad.x) - mx.x) * inv.x;
            al.y = expf(lrelu(as.y + ad.y) - mx.y) * inv.y;
            al.z = expf(lrelu(as.z + ad.z) - mx.z) * inv.z;
            al.w = expf(lrelu(as.w + ad.w) - mx.w) * inv.w;
            ssrc[tid] = s;
            sal[tid] = al;
        }
        __syncthreads();
        for (int jj = 0; jj < cnt; jj++) {
            const float* h = g_H1 + (size_t)ssrc[jj] * 2048 + 2 * tid;
            float4 al = sal[jj];
            float2 v0 = __ldg((const float2*)(h));
            float2 v1 = __ldg((const float2*)(h + 512));
            float2 v2 = __ldg((const float2*)(h + 1024));
            float2 v3 = __ldg((const float2*)(h + 1536));
            acc.x += al.x * v0.x + al.y * v1.x + al.z * v2.x + al.w * v3.x;
            acc.y += al.x * v0.y + al.y * v1.y + al.z * v2.y + al.w * v3.y;
        }
    }
    *(float2*)(g_out1 + (size_t)d * 512 + 2 * tid) = acc;
}

// ---------------------------------------------------------------------------
// BatchNorm stats (b1 BN-invariant -> skipped) + normalize + ELU
// ---------------------------------------------------------------------------
__global__ void k_bnstats(int Nn) {
    int c = blockIdx.x * blockDim.x + threadIdx.x;   // 0..511
    int r0 = blockIdx.y * 64;
    int r1 = min(r0 + 64, Nn);
    float s1 = 0.f, s2 = 0.f;
    for (int r = r0; r < r1; r++) {
        float v = g_out1[(size_t)r * 512 + c];
        s1 += v;
        s2 = fmaf(v, v, s2);
    }
    atomicAdd(&g_stats[c], s1);
    atomicAdd(&g_stats[512 + c], s2);
}

__global__ void k_bnelu(const float* __restrict__ gamma, const float* __restrict__ beta,
                        int Nn, float invN) {
    size_t total = (size_t)Nn * 512;
    for (size_t i = (size_t)blockIdx.x * blockDim.x + threadIdx.x; i < total;
         i += (size_t)gridDim.x * blockDim.x) {
        int c = (int)(i & 511);
        float mu = g_stats[c] * invN;
        float var = g_stats[512 + c] * invN - mu * mu;
        float x = (g_out1[i] - mu) * rsqrtf(var + 1e-5f) * gamma[c] + beta[c];
        g_hmid[i] = x > 0.f ? x : expm1f(x);
    }
}

// ---------------------------------------------------------------------------
// layer-2 prep: H2 = hmid @ W2 (one warp per row) + attention scalars
// ---------------------------------------------------------------------------
__global__ void k_l2prep(const float* __restrict__ W2, const float* __restrict__ as2,
                         const float* __restrict__ ad2, int Nn) {
    int gw = (int)(((size_t)blockIdx.x * blockDim.x + threadIdx.x) >> 5);
    int lane = threadIdx.x & 31;
    if (gw >= Nn) return;
    const float* h = g_hmid + (size_t)gw * 512;
    float acc = 0.f;
    for (int kb = 0; kb < 16; kb++) {
        float hv = h[kb * 32 + lane];
#pragma unroll
        for (int j = 0; j < 32; j++) {
            float hk = __shfl_sync(0xffffffffu, hv, j);
            float w = (lane < 30) ? __ldg(W2 + (size_t)(kb * 32 + j) * 30 + lane) : 0.f;
            acc = fmaf(hk, w, acc);
        }
    }
    float sa = (lane < 30) ? acc * __ldg(as2 + lane) : 0.f;
    float sd = (lane < 30) ? acc * __ldg(ad2 + lane) : 0.f;
#pragma unroll
    for (int off = 16; off; off >>= 1) {
        sa += __shfl_down_sync(0xffffffffu, sa, off);
        sd += __shfl_down_sync(0xffffffffu, sd, off);
    }
    if (lane < 30) g_H2[(size_t)gw * 30 + lane] = acc;
    if (lane == 0) { g_asrc2[gw] = sa; g_adst2[gw] = sd; }
}

// ---------------------------------------------------------------------------
// layer-2 edge passes (H=1, C=30)
// ---------------------------------------------------------------------------
__global__ void k_edge_max2(const int* __restrict__ ei, int E, int Nn) {
    int e = blockIdx.x * blockDim.x + threadIdx.x;
    if (e >= E + Nn) return;
    int s, d;
    if (e < E) { s = ei[e]; d = ei[E + e]; } else { s = d = e - E; }
    float v = lrelu(g_asrc2[s] + g_adst2[d]);
    g_e2[e] = v;
    atomicMax(&g_max2[d], f2ord(v));
}

__global__ void k_exp2(const int* __restrict__ ei, int E, int Nn) {
    int e = blockIdx.x * blockDim.x + threadIdx.x;
    if (e >= E + Nn) return;
    int d = (e < E) ? ei[E + e] : e - E;
    float ex = expf(g_e2[e] - ord2f(g_max2[d]));
    g_e2[e] = ex;
    atomicAdd(&g_sum2[d], ex);
}

__global__ void k_msg2(const int* __restrict__ ei, int E, int Nn, float* __restrict__ out) {
    int gw = (int)(((size_t)blockIdx.x * blockDim.x + threadIdx.x) >> 5);
    int lane = threadIdx.x & 31;
    if (gw >= E + Nn) return;
    int s, d;
    if (gw < E) { s = ei[gw]; d = ei[E + gw]; } else { s = d = gw - E; }
    float al = g_e2[gw] / (g_sum2[d] + 1e-16f);
    if (lane < 30)
        atomicAdd(out + (size_t)d * 30 + lane, al * __ldg(g_H2 + (size_t)s * 30 + lane));
}

// ---------------------------------------------------------------------------
// launch
// ---------------------------------------------------------------------------
extern "C" void kernel_launch(void* const* d_in, const int* in_sizes, int n_in,
                              void* d_out, int out_size) {
    const float* x       = (const float*)d_in[0];
    const int*   ei      = (const int*)d_in[1];
    const float* W1      = (const float*)d_in[2];
    const float* attsrc1 = (const float*)d_in[3];
    const float* attdst1 = (const float*)d_in[4];
    // d_in[5] = b1: BN-invariant, skipped
    const float* gamma   = (const float*)d_in[6];
    const float* beta    = (const float*)d_in[7];
    const float* W2      = (const float*)d_in[8];
    const float* attsrc2 = (const float*)d_in[9];
    const float* attdst2 = (const float*)d_in[10];
    const float* b2      = (const float*)d_in[11];
    float* out = (float*)d_out;

    int Nn = in_sizes[0] / 2000;
    int E  = in_sizes[1] / 2;
    int Etot = E + Nn;
    int eb = (Etot + 255) / 256;

    cudaFuncSetAttribute(k_gemm1, cudaFuncAttributeMaxDynamicSharedMemorySize, SMEM_GEMM);

    k_init<<<2048, 256>>>(out, b2, Nn);
    k_roundA<<<2048, 256>>>(x, (size_t)Nn * 2000 / 4);
    k_roundB<<<1024, 256>>>(W1, (size_t)2000 * 2048 / 4);
    k_deg<<<eb, 256>>>(ei, E, Nn);
    k_scan<<<1, 1024>>>(Nn);
    k_scatter<<<eb, 256>>>(ei, E, Nn);

    dim3 g1(2048 / 128, (Nn + 255) / 256);   // x fastest: col-tiles share A rows in L2
    k_gemm1<<<g1, 256, SMEM_GEMM>>>(Nn);

    k_att1<<<(Nn * 4 * 32 + 255) / 256, 256>>>(attsrc1, attdst1, Nn);

    k_agg1<<<Nn, 256>>>(Nn);

    dim3 gs(2, (Nn + 63) / 64);
    k_bnstats<<<gs, 256>>>(Nn);
    k_bnelu<<<4096, 256>>>(gamma, beta, Nn, 1.f / (float)Nn);

    k_l2prep<<<(int)(((size_t)Nn * 32 + 255) / 256), 256>>>(W2, attsrc2, attdst2, Nn);

    k_edge_max2<<<eb, 256>>>(ei, E, Nn);
    k_exp2<<<eb, 256>>>(ei, E, Nn);
    int mb = (int)(((size_t)Etot * 32 + 255) / 256);
    k_msg2<<<mb, 256>>>(ei, E, Nn, out);
}

// round 12
// speedup vs baseline: 1.3365x; 1.3365x over previous
#include <cuda_runtime.h>
#include <cuda_fp16.h>
#include <cstdint>
#include <cstddef>

// ---------------------------------------------------------------------------
// GATEncoder: GATConv(2000->4x512, mean heads) -> BN -> ELU -> GATConv(512->30)
// N=50000, F=2000, H=4, C=512, LAT=30, E=800000 (+N self loops)
// R12: R11 with the fictional __half2_as_uint intrinsic replaced by a
//      __half2_raw bit-cast helper. fp16 m16n8k16 HMMA GEMM1 (2x tf32 rate,
//      same 11-bit significand), ldmatrix.x4, BM=128/BN=128/BK=32, 4 stages,
//      2 CTAs/SM. Everything else identical to the 3845us R3 configuration.
// ---------------------------------------------------------------------------

#define NMAX 50000
#define EMAX 800000
#define ETMAX (EMAX + NMAX)

#define GEMM_STAGES 4
#define ROW_BYTES 80                       // 32 halfs (64B) + 16B pad: LDSM conflict-free
#define OP_TILE (128 * ROW_BYTES)          // 10240 B per operand per stage
#define STAGE_BYTES (2 * OP_TILE)          // 20480
#define SMEM_GEMM (GEMM_STAGES * STAGE_BYTES)   // 81920

// ---- device scratch (static; no runtime allocation allowed) ----
__device__ float    g_H1[(size_t)NMAX * 2048];    // x @ W1
__device__ __half   g_Ah[(size_t)NMAX * 2000];    // x in fp16
__device__ __half   g_W1h[(size_t)2048 * 2000];   // W1^T in fp16 ([n][k])
__device__ float    g_out1[(size_t)NMAX * 512];   // layer-1 aggregate
__device__ float    g_hmid[(size_t)NMAX * 512];   // after BN+ELU
__device__ float    g_H2[(size_t)NMAX * 30];      // hmid @ W2
__device__ float    g_asrc1[NMAX * 4];
__device__ float    g_adst1[NMAX * 4];
__device__ float    g_asrc2[NMAX];
__device__ float    g_adst2[NMAX];
__device__ unsigned g_max2[NMAX];
__device__ float    g_sum2[NMAX];
__device__ float    g_e2[ETMAX];
__device__ float    g_stats[1024];                // [0:512) sum, [512:1024) sumsq
// CSR by destination
__device__ int      g_deg[NMAX];
__device__ int      g_rowptr[NMAX + 1];
__device__ int      g_woff[NMAX];
__device__ int      g_csr_src[ETMAX];

// ---- helpers ----
__device__ __forceinline__ uint32_t h2u(__half2 h) {
    __half2_raw r = *reinterpret_cast<__half2_raw*>(&h);
    return (uint32_t)r.x | ((uint32_t)r.y << 16);
}
__device__ __forceinline__ unsigned f2ord(float f) {
    unsigned u = __float_as_uint(f);
    return (u & 0x80000000u) ? ~u : (u | 0x80000000u);
}
__device__ __forceinline__ float ord2f(unsigned u) {
    unsigned b = (u & 0x80000000u) ? (u & 0x7FFFFFFFu) : ~u;
    return __uint_as_float(b);
}
__device__ __forceinline__ float lrelu(float v) { return v > 0.f ? v : 0.2f * v; }

__device__ __forceinline__ void cp16(uint32_t saddr, const void* gptr, bool pred) {
    int sz = pred ? 16 : 0;   // sz=0 -> 16 bytes zero-filled (src-size form)
    asm volatile("cp.async.cg.shared.global [%0], [%1], 16, %2;\n"
                 :: "r"(saddr), "l"(gptr), "r"(sz));
}
__device__ __forceinline__ void cp_commit() {
    asm volatile("cp.async.commit_group;\n" ::: "memory");
}
__device__ __forceinline__ void cp_waitg() {
    asm volatile("cp.async.wait_group %0;\n" :: "n"(GEMM_STAGES - 2) : "memory");
}
__device__ __forceinline__ void ldsm4(uint32_t* r, uint32_t addr) {
    asm volatile("ldmatrix.sync.aligned.m8n8.x4.shared.b16 {%0,%1,%2,%3}, [%4];"
                 : "=r"(r[0]), "=r"(r[1]), "=r"(r[2]), "=r"(r[3]) : "r"(addr));
}

// ---------------------------------------------------------------------------
// init
// ---------------------------------------------------------------------------
__global__ void k_init(float* __restrict__ out, const float* __restrict__ b2, int Nn) {
    size_t total = (size_t)Nn * 30;
    for (size_t i = (size_t)blockIdx.x * blockDim.x + threadIdx.x; i < total;
         i += (size_t)gridDim.x * blockDim.x) {
        if (i < (size_t)Nn) { g_deg[i] = 0; g_sum2[i] = 0.f; g_max2[i] = 0u; }
        if (i < 1024) g_stats[i] = 0.f;
        out[i] = b2[i % 30];
    }
}

// ---------------------------------------------------------------------------
// conversions: x -> fp16 ; W1 -> fp16 transposed [n][k]
// ---------------------------------------------------------------------------
__global__ void k_cvtA(const float* __restrict__ x, size_t n8) {
    const float4* src = (const float4*)x;
    uint4* dst = (uint4*)g_Ah;
    for (size_t i = (size_t)blockIdx.x * blockDim.x + threadIdx.x; i < n8;
         i += (size_t)gridDim.x * blockDim.x) {
        float4 v0 = __ldg(src + 2 * i);
        float4 v1 = __ldg(src + 2 * i + 1);
        uint4 o;
        o.x = h2u(__floats2half2_rn(v0.x, v0.y));
        o.y = h2u(__floats2half2_rn(v0.z, v0.w));
        o.z = h2u(__floats2half2_rn(v1.x, v1.y));
        o.w = h2u(__floats2half2_rn(v1.z, v1.w));
        dst[i] = o;
    }
}

__global__ void k_cvtBT(const float* __restrict__ W1) {
    __shared__ float t[32][33];
    int n0 = blockIdx.x * 32, k0 = blockIdx.y * 32;
    int tx = threadIdx.x, ty = threadIdx.y;   // 32 x 8
#pragma unroll
    for (int i = 0; i < 32; i += 8) {
        int k = k0 + ty + i;
        t[ty + i][tx] = (k < 2000) ? W1[(size_t)k * 2048 + n0 + tx] : 0.f;
    }
    __syncthreads();
#pragma unroll
    for (int i = 0; i < 32; i += 8) {
        int k = k0 + tx;
        if (k < 2000)
            g_W1h[(size_t)(n0 + ty + i) * 2000 + k] = __float2half_rn(t[tx][ty + i]);
    }
}

// ---------------------------------------------------------------------------
// CSR build: degree count -> exclusive scan -> scatter (src indices)
// ---------------------------------------------------------------------------
__global__ void k_deg(const int* __restrict__ ei, int E, int Nn) {
    int e = blockIdx.x * blockDim.x + threadIdx.x;
    if (e >= E + Nn) return;
    int d = (e < E) ? ei[E + e] : e - E;
    atomicAdd(&g_deg[d], 1);
}

__global__ void k_scan(int Nn) {
    __shared__ int wsum[32];
    __shared__ int carry_s;
    int tid = threadIdx.x;
    if (tid == 0) carry_s = 0;
    __syncthreads();
    int iters = (Nn + 1023) / 1024;
    for (int it = 0; it < iters; it++) {
        int i = it * 1024 + tid;
        int v = (i < Nn) ? g_deg[i] : 0;
        int x = v;
#pragma unroll
        for (int o = 1; o < 32; o <<= 1) {
            int y = __shfl_up_sync(0xffffffffu, x, o);
            if ((tid & 31) >= o) x += y;
        }
        if ((tid & 31) == 31) wsum[tid >> 5] = x;
        __syncthreads();
        if (tid < 32) {
            int w = wsum[tid];
#pragma unroll
            for (int o = 1; o < 32; o <<= 1) {
                int y = __shfl_up_sync(0xffffffffu, w, o);
                if (tid >= o) w += y;
            }
            wsum[tid] = w;
        }
        __syncthreads();
        int warp = tid >> 5;
        int incl = x + (warp ? wsum[warp - 1] : 0);
        int excl = incl - v;
        int c = carry_s;
        if (i < Nn) { g_rowptr[i] = c + excl; g_woff[i] = c + excl; }
        __syncthreads();
        if (tid == 1023) carry_s = c + incl;
        __syncthreads();
    }
    if (tid == 0) g_rowptr[Nn] = carry_s;
}

__global__ void k_scatter(const int* __restrict__ ei, int E, int Nn) {
    int e = blockIdx.x * blockDim.x + threadIdx.x;
    if (e >= E + Nn) return;
    int s, d;
    if (e < E) { s = ei[e]; d = ei[E + e]; } else { s = d = e - E; }
    int pos = atomicAdd(&g_woff[d], 1);
    g_csr_src[pos] = s;
}

// ---------------------------------------------------------------------------
// GEMM1: g_H1[M,2048] = Ah[M,2000] @ W1h^T  (fp16 mma.m16n8k16, f32 accum)
// BM=128 BN=128 BK=32, 256 thr = 8 warps (4m x 2n), warp tile 32x64,
// 4-stage cp.async, ldmatrix.x4 fragment loads, 2 CTAs/SM.
// ---------------------------------------------------------------------------
__global__ __launch_bounds__(256, 2)
void k_gemm1h(int M) {
    extern __shared__ char smem[];
    const uint32_t sb = (uint32_t)__cvta_generic_to_shared(smem);
    const __half* A = g_Ah;
    const __half* B = g_W1h;

    const int tid  = threadIdx.x;
    const int lane = tid & 31, warp = tid >> 5;
    const int gid  = lane >> 2, tig = lane & 3;
    const int wm   = warp >> 1, wn = warp & 1;
    const int rowBase = blockIdx.y * 128;
    const int colBase = blockIdx.x * 128;
    const int KITERS = 63;   // ceil(2000/32); tail chunks zero-filled by cp.async

    // ldmatrix lane addressing: row-in-16 and k8-group
    const int mrow = (lane & 7) + ((lane >> 3) & 1) * 8;
    const int koff = ((lane >> 4) & 1) * 16;

    float acc[2][8][4];
#pragma unroll
    for (int i = 0; i < 2; i++)
#pragma unroll
        for (int j = 0; j < 8; j++)
#pragma unroll
            for (int k = 0; k < 4; k++) acc[i][j][k] = 0.f;

    auto load_tile = [&](int st, int k0) {
        uint32_t aBase = sb + st * STAGE_BYTES;
        uint32_t bBase = aBase + OP_TILE;
#pragma unroll
        for (int i = 0; i < 2; i++) {
            int idx = tid + i * 256;
            int r = idx >> 2, j = idx & 3;
            int gr = rowBase + r;
            bool p = (gr < M) && (k0 + j * 8 < 2000);
            cp16(aBase + r * ROW_BYTES + j * 16, A + (size_t)gr * 2000 + k0 + j * 8, p);
        }
#pragma unroll
        for (int i = 0; i < 2; i++) {
            int idx = tid + i * 256;
            int r = idx >> 2, j = idx & 3;
            bool p = (k0 + j * 8 < 2000);
            cp16(bBase + r * ROW_BYTES + j * 16,
                 B + (size_t)(colBase + r) * 2000 + k0 + j * 8, p);
        }
    };

#pragma unroll
    for (int s = 0; s < GEMM_STAGES - 1; s++) {
        load_tile(s, s * 32);
        cp_commit();
    }

    for (int it = 0; it < KITERS; it++) {
        cp_waitg();
        __syncthreads();
        int st = it & (GEMM_STAGES - 1);
        uint32_t aBase = sb + st * STAGE_BYTES;
        uint32_t bBase = aBase + OP_TILE;
#pragma unroll
        for (int ks = 0; ks < 2; ks++) {
            uint32_t a[2][4], bf[4][4];
#pragma unroll
            for (int tm = 0; tm < 2; tm++) {
                uint32_t addr = aBase + (wm * 32 + tm * 16 + mrow) * ROW_BYTES
                              + ks * 32 + koff;
                ldsm4(a[tm], addr);
            }
#pragma unroll
            for (int tp = 0; tp < 4; tp++) {
                uint32_t addr = bBase + (wn * 64 + tp * 16 + mrow) * ROW_BYTES
                              + ks * 32 + koff;
                ldsm4(bf[tp], addr);
            }
#pragma unroll
            for (int tm = 0; tm < 2; tm++)
#pragma unroll
                for (int tp = 0; tp < 4; tp++) {
                    asm volatile(
                        "mma.sync.aligned.m16n8k16.row.col.f32.f16.f16.f32 "
                        "{%0,%1,%2,%3},{%4,%5,%6,%7},{%8,%9},{%0,%1,%2,%3};\n"
                        : "+f"(acc[tm][tp * 2][0]), "+f"(acc[tm][tp * 2][1]),
                          "+f"(acc[tm][tp * 2][2]), "+f"(acc[tm][tp * 2][3])
                        : "r"(a[tm][0]), "r"(a[tm][1]), "r"(a[tm][2]), "r"(a[tm][3]),
                          "r"(bf[tp][0]), "r"(bf[tp][2]));
                    asm volatile(
                        "mma.sync.aligned.m16n8k16.row.col.f32.f16.f16.f32 "
                        "{%0,%1,%2,%3},{%4,%5,%6,%7},{%8,%9},{%0,%1,%2,%3};\n"
                        : "+f"(acc[tm][tp * 2 + 1][0]), "+f"(acc[tm][tp * 2 + 1][1]),
                          "+f"(acc[tm][tp * 2 + 1][2]), "+f"(acc[tm][tp * 2 + 1][3])
                        : "r"(a[tm][0]), "r"(a[tm][1]), "r"(a[tm][2]), "r"(a[tm][3]),
                          "r"(bf[tp][1]), "r"(bf[tp][3]));
                }
        }
        int nit = it + GEMM_STAGES - 1;
        if (nit < KITERS) load_tile(nit & (GEMM_STAGES - 1), nit * 32);
        cp_commit();
    }

    // epilogue: c0,c1 -> (row gid, cols 2tig..+1); c2,c3 -> row gid+8
#pragma unroll
    for (int tm = 0; tm < 2; tm++) {
        int r0 = rowBase + wm * 32 + tm * 16 + gid;
#pragma unroll
        for (int tn = 0; tn < 8; tn++) {
            int c = colBase + wn * 64 + tn * 8 + tig * 2;
            if (r0 < M) {
                g_H1[(size_t)r0 * 2048 + c]     = acc[tm][tn][0];
                g_H1[(size_t)r0 * 2048 + c + 1] = acc[tm][tn][1];
            }
            if (r0 + 8 < M) {
                g_H1[(size_t)(r0 + 8) * 2048 + c]     = acc[tm][tn][2];
                g_H1[(size_t)(r0 + 8) * 2048 + c + 1] = acc[tm][tn][3];
            }
        }
    }
}

// ---------------------------------------------------------------------------
// attention dots layer 1: a_src/a_dst[n,h] = <H1[n,h,:], att[h,:]>
// ---------------------------------------------------------------------------
__global__ void k_att1(const float* __restrict__ att_src, const float* __restrict__ att_dst,
                       int Nn) {
    int gw = (int)(((size_t)blockIdx.x * blockDim.x + threadIdx.x) >> 5);
    int lane = threadIdx.x & 31;
    if (gw >= Nn * 4) return;
    int n = gw >> 2, h = gw & 3;
    const float4* r4 = (const float4*)(g_H1 + (size_t)n * 2048 + h * 512);
    const float4* s4 = (const float4*)(att_src + h * 512);
    const float4* d4 = (const float4*)(att_dst + h * 512);
    float ss = 0.f, dd = 0.f;
#pragma unroll 4
    for (int i = lane; i < 128; i += 32) {
        float4 v = r4[i], a = s4[i], b = d4[i];
        ss += v.x * a.x + v.y * a.y + v.z * a.z + v.w * a.w;
        dd += v.x * b.x + v.y * b.y + v.z * b.z + v.w * b.w;
    }
#pragma unroll
    for (int off = 16; off; off >>= 1) {
        ss += __shfl_down_sync(0xffffffffu, ss, off);
        dd += __shfl_down_sync(0xffffffffu, dd, off);
    }
    if (lane == 0) { g_asrc1[gw] = ss; g_adst1[gw] = dd; }
}

// ---------------------------------------------------------------------------
// fused layer-1 softmax + aggregation: one block (256 thr) per destination.
// ---------------------------------------------------------------------------
__global__ __launch_bounds__(256)
void k_agg1(int Nn) {
    const int d = blockIdx.x;
    const int tid = threadIdx.x, lane = tid & 31, warp = tid >> 5;
    const int beg = g_rowptr[d], end = g_rowptr[d + 1];

    __shared__ float4 rwarp[8];
    __shared__ float4 rbc;
    __shared__ int    ssrc[256];
    __shared__ float4 sal[256];

    float4 ad = *(const float4*)(g_adst1 + (size_t)d * 4);
    const float NEGINF = __int_as_float(0xff800000);

    float4 mx = make_float4(NEGINF, NEGINF, NEGINF, NEGINF);
    for (int j = beg + tid; j < end; j += 256) {
        int s = g_csr_src[j];
        float4 as = *(const float4*)(g_asrc1 + (size_t)s * 4);
        mx.x = fmaxf(mx.x, lrelu(as.x + ad.x));
        mx.y = fmaxf(mx.y, lrelu(as.y + ad.y));
        mx.z = fmaxf(mx.z, lrelu(as.z + ad.z));
        mx.w = fmaxf(mx.w, lrelu(as.w + ad.w));
    }
#pragma unroll
    for (int o = 16; o; o >>= 1) {
        mx.x = fmaxf(mx.x, __shfl_down_sync(0xffffffffu, mx.x, o));
        mx.y = fmaxf(mx.y, __shfl_down_sync(0xffffffffu, mx.y, o));
        mx.z = fmaxf(mx.z, __shfl_down_sync(0xffffffffu, mx.z, o));
        mx.w = fmaxf(mx.w, __shfl_down_sync(0xffffffffu, mx.w, o));
    }
    if (lane == 0) rwarp[warp] = mx;
    __syncthreads();
    if (tid == 0) {
        float4 m = rwarp[0];
#pragma unroll
        for (int w = 1; w < 8; w++) {
            m.x = fmaxf(m.x, rwarp[w].x); m.y = fmaxf(m.y, rwarp[w].y);
            m.z = fmaxf(m.z, rwarp[w].z); m.w = fmaxf(m.w, rwarp[w].w);
        }
        rbc = m;
    }
    __syncthreads();
    mx = rbc;

    float4 sm = make_float4(0.f, 0.f, 0.f, 0.f);
    for (int j = beg + tid; j < end; j += 256) {
        int s = g_csr_src[j];
        float4 as = *(const float4*)(g_asrc1 + (size_t)s * 4);
        sm.x += expf(lrelu(as.x + ad.x) - mx.x);
        sm.y += expf(lrelu(as.y + ad.y) - mx.y);
        sm.z += expf(lrelu(as.z + ad.z) - mx.z);
        sm.w += expf(lrelu(as.w + ad.w) - mx.w);
    }
#pragma unroll
    for (int o = 16; o; o >>= 1) {
        sm.x += __shfl_down_sync(0xffffffffu, sm.x, o);
        sm.y += __shfl_down_sync(0xffffffffu, sm.y, o);
        sm.z += __shfl_down_sync(0xffffffffu, sm.z, o);
        sm.w += __shfl_down_sync(0xffffffffu, sm.w, o);
    }
    if (lane == 0) rwarp[warp] = sm;
    __syncthreads();
    if (tid == 0) {
        float4 t = rwarp[0];
#pragma unroll
        for (int w = 1; w < 8; w++) {
            t.x += rwarp[w].x; t.y += rwarp[w].y; t.z += rwarp[w].z; t.w += rwarp[w].w;
        }
        rbc = t;
    }
    __syncthreads();
    sm = rbc;
    float4 inv;
    inv.x = 0.25f / (sm.x + 1e-16f);
    inv.y = 0.25f / (sm.y + 1e-16f);
    inv.z = 0.25f / (sm.z + 1e-16f);
    inv.w = 0.25f / (sm.w + 1e-16f);

    float2 acc = make_float2(0.f, 0.f);
    for (int c0 = beg; c0 < end; c0 += 256) {
        int cnt = min(end - c0, 256);
        __syncthreads();
        if (tid < cnt) {
            int s = g_csr_src[c0 + tid];
            float4 as = *(const float4*)(g_asrc1 + (size_t)s * 4);
            float4 al;
            al.x = expf(lrelu(as.x + ad.x) - mx.x) * inv.x;
            al.y = expf(lrelu(as.y + ad.y) - mx.y) * inv.y;
            al.z = expf(lrelu(as.z + ad.z) - mx.z) * inv.z;
            al.w = expf(lrelu(as.w + ad.w) - mx.w) * inv.w;
            ssrc[tid] = s;
            sal[tid] = al;
        }
        __syncthreads();
        for (int jj = 0; jj < cnt; jj++) {
            const float* h = g_H1 + (size_t)ssrc[jj] * 2048 + 2 * tid;
            float4 al = sal[jj];
            float2 v0 = __ldg((const float2*)(h));
            float2 v1 = __ldg((const float2*)(h + 512));
            float2 v2 = __ldg((const float2*)(h + 1024));
            float2 v3 = __ldg((const float2*)(h + 1536));
            acc.x += al.x * v0.x + al.y * v1.x + al.z * v2.x + al.w * v3.x;
            acc.y += al.x * v0.y + al.y * v1.y + al.z * v2.y + al.w * v3.y;
        }
    }
    *(float2*)(g_out1 + (size_t)d * 512 + 2 * tid) = acc;
}

// ---------------------------------------------------------------------------
// BatchNorm stats (b1 BN-invariant -> skipped) + normalize + ELU
// ---------------------------------------------------------------------------
__global__ void k_bnstats(int Nn) {
    int c = blockIdx.x * blockDim.x + threadIdx.x;   // 0..511
    int r0 = blockIdx.y * 64;
    int r1 = min(r0 + 64, Nn);
    float s1 = 0.f, s2 = 0.f;
    for (int r = r0; r < r1; r++) {
        float v = g_out1[(size_t)r * 512 + c];
        s1 += v;
        s2 = fmaf(v, v, s2);
    }
    atomicAdd(&g_stats[c], s1);
    atomicAdd(&g_stats[512 + c], s2);
}

__global__ void k_bnelu(const float* __restrict__ gamma, const float* __restrict__ beta,
                        int Nn, float invN) {
    size_t total = (size_t)Nn * 512;
    for (size_t i = (size_t)blockIdx.x * blockDim.x + threadIdx.x; i < total;
         i += (size_t)gridDim.x * blockDim.x) {
        int c = (int)(i & 511);
        float mu = g_stats[c] * invN;
        float var = g_stats[512 + c] * invN - mu * mu;
        float x = (g_out1[i] - mu) * rsqrtf(var + 1e-5f) * gamma[c] + beta[c];
        g_hmid[i] = x > 0.f ? x : expm1f(x);
    }
}

// ---------------------------------------------------------------------------
// layer-2 prep: H2 = hmid @ W2 (one warp per row) + attention scalars
// ---------------------------------------------------------------------------
__global__ void k_l2prep(const float* __restrict__ W2, const float* __restrict__ as2,
                         const float* __restrict__ ad2, int Nn) {
    int gw = (int)(((size_t)blockIdx.x * blockDim.x + threadIdx.x) >> 5);
    int lane = threadIdx.x & 31;
    if (gw >= Nn) return;
    const float* h = g_hmid + (size_t)gw * 512;
    float acc = 0.f;
    for (int kb = 0; kb < 16; kb++) {
        float hv = h[kb * 32 + lane];
#pragma unroll
        for (int j = 0; j < 32; j++) {
            float hk = __shfl_sync(0xffffffffu, hv, j);
            float w = (lane < 30) ? __ldg(W2 + (size_t)(kb * 32 + j) * 30 + lane) : 0.f;
            acc = fmaf(hk, w, acc);
        }
    }
    float sa = (lane < 30) ? acc * __ldg(as2 + lane) : 0.f;
    float sd = (lane < 30) ? acc * __ldg(ad2 + lane) : 0.f;
#pragma unroll
    for (int off = 16; off; off >>= 1) {
        sa += __shfl_down_sync(0xffffffffu, sa, off);
        sd += __shfl_down_sync(0xffffffffu, sd, off);
    }
    if (lane < 30) g_H2[(size_t)gw * 30 + lane] = acc;
    if (lane == 0) { g_asrc2[gw] = sa; g_adst2[gw] = sd; }
}

// ---------------------------------------------------------------------------
// layer-2 edge passes (H=1, C=30)
// ---------------------------------------------------------------------------
__global__ void k_edge_max2(const int* __restrict__ ei, int E, int Nn) {
    int e = blockIdx.x * blockDim.x + threadIdx.x;
    if (e >= E + Nn) return;
    int s, d;
    if (e < E) { s = ei[e]; d = ei[E + e]; } else { s = d = e - E; }
    float v = lrelu(g_asrc2[s] + g_adst2[d]);
    g_e2[e] = v;
    atomicMax(&g_max2[d], f2ord(v));
}

__global__ void k_exp2(const int* __restrict__ ei, int E, int Nn) {
    int e = blockIdx.x * blockDim.x + threadIdx.x;
    if (e >= E + Nn) return;
    int d = (e < E) ? ei[E + e] : e - E;
    float ex = expf(g_e2[e] - ord2f(g_max2[d]));
    g_e2[e] = ex;
    atomicAdd(&g_sum2[d], ex);
}

__global__ void k_msg2(const int* __restrict__ ei, int E, int Nn, float* __restrict__ out) {
    int gw = (int)(((size_t)blockIdx.x * blockDim.x + threadIdx.x) >> 5);
    int lane = threadIdx.x & 31;
    if (gw >= E + Nn) return;
    int s, d;
    if (gw < E) { s = ei[gw]; d = ei[E + gw]; } else { s = d = gw - E; }
    float al = g_e2[gw] / (g_sum2[d] + 1e-16f);
    if (lane < 30)
        atomicAdd(out + (size_t)d * 30 + lane, al * __ldg(g_H2 + (size_t)s * 30 + lane));
}

// ---------------------------------------------------------------------------
// launch
// ---------------------------------------------------------------------------
extern "C" void kernel_launch(void* const* d_in, const int* in_sizes, int n_in,
                              void* d_out, int out_size) {
    const float* x       = (const float*)d_in[0];
    const int*   ei      = (const int*)d_in[1];
    const float* W1      = (const float*)d_in[2];
    const float* attsrc1 = (const float*)d_in[3];
    const float* attdst1 = (const float*)d_in[4];
    // d_in[5] = b1: BN-invariant, skipped
    const float* gamma   = (const float*)d_in[6];
    const float* beta    = (const float*)d_in[7];
    const float* W2      = (const float*)d_in[8];
    const float* attsrc2 = (const float*)d_in[9];
    const float* attdst2 = (const float*)d_in[10];
    const float* b2      = (const float*)d_in[11];
    float* out = (float*)d_out;

    int Nn = in_sizes[0] / 2000;
    int E  = in_sizes[1] / 2;
    int Etot = E + Nn;
    int eb = (Etot + 255) / 256;

    cudaFuncSetAttribute(k_gemm1h, cudaFuncAttributeMaxDynamicSharedMemorySize, SMEM_GEMM);

    k_init<<<2048, 256>>>(out, b2, Nn);
    k_cvtA<<<2048, 256>>>(x, (size_t)Nn * 2000 / 8);
    k_cvtBT<<<dim3(64, 63), dim3(32, 8)>>>(W1);
    k_deg<<<eb, 256>>>(ei, E, Nn);
    k_scan<<<1, 1024>>>(Nn);
    k_scatter<<<eb, 256>>>(ei, E, Nn);

    dim3 g1(16, (Nn + 127) / 128);   // x = col tiles (share A rows in L2)
    k_gemm1h<<<g1, 256, SMEM_GEMM>>>(Nn);

    k_att1<<<(Nn * 4 * 32 + 255) / 256, 256>>>(attsrc1, attdst1, Nn);

    k_agg1<<<Nn, 256>>>(Nn);

    dim3 gs(2, (Nn + 63) / 64);
    k_bnstats<<<gs, 256>>>(Nn);
    k_bnelu<<<4096, 256>>>(gamma, beta, Nn, 1.f / (float)Nn);

    k_l2prep<<<(int)(((size_t)Nn * 32 + 255) / 256), 256>>>(W2, attsrc2, attdst2, Nn);

    k_edge_max2<<<eb, 256>>>(ei, E, Nn);
    k_exp2<<<eb, 256>>>(ei, E, Nn);
    int mb = (int)(((size_t)Etot * 32 + 255) / 256);
    k_msg2<<<mb, 256>>>(ei, E, Nn, out);
}

// round 13
// speedup vs baseline: 1.4871x; 1.1126x over previous
#include <cuda_runtime.h>
#include <cuda_fp16.h>
#include <cstdint>
#include <cstddef>

// ---------------------------------------------------------------------------
// GATEncoder: GATConv(2000->4x512, mean heads) -> BN -> ELU -> GATConv(512->30)
// N=50000, F=2000, H=4, C=512, LAT=30, E=800000 (+N self loops)
// R13: H1 stored in fp16 (halves the k_agg1 DRAM gather floor, the largest
//      remaining kernel). fp16 m16n8k16 GEMM1 unchanged from the 3008us R12.
// ---------------------------------------------------------------------------

#define NMAX 50000
#define EMAX 800000
#define ETMAX (EMAX + NMAX)

#define GEMM_STAGES 4
#define ROW_BYTES 80                       // 32 halfs (64B) + 16B pad: LDSM conflict-free
#define OP_TILE (128 * ROW_BYTES)          // 10240 B per operand per stage
#define STAGE_BYTES (2 * OP_TILE)          // 20480
#define SMEM_GEMM (GEMM_STAGES * STAGE_BYTES)   // 81920

// ---- device scratch (static; no runtime allocation allowed) ----
__device__ __half   g_H1h[(size_t)NMAX * 2048];   // x @ W1 in fp16 (204.8 MB)
__device__ __half   g_Ah[(size_t)NMAX * 2000];    // x in fp16
__device__ __half   g_W1h[(size_t)2048 * 2000];   // W1^T in fp16 ([n][k])
__device__ float    g_out1[(size_t)NMAX * 512];   // layer-1 aggregate
__device__ float    g_hmid[(size_t)NMAX * 512];   // after BN+ELU
__device__ float    g_H2[(size_t)NMAX * 30];      // hmid @ W2
__device__ float    g_asrc1[NMAX * 4];
__device__ float    g_adst1[NMAX * 4];
__device__ float    g_asrc2[NMAX];
__device__ float    g_adst2[NMAX];
__device__ unsigned g_max2[NMAX];
__device__ float    g_sum2[NMAX];
__device__ float    g_e2[ETMAX];
__device__ float    g_stats[1024];                // [0:512) sum, [512:1024) sumsq
// CSR by destination
__device__ int      g_deg[NMAX];
__device__ int      g_rowptr[NMAX + 1];
__device__ int      g_woff[NMAX];
__device__ int      g_csr_src[ETMAX];

// ---- helpers ----
__device__ __forceinline__ uint32_t h2u(__half2 h) {
    __half2_raw r = *reinterpret_cast<__half2_raw*>(&h);
    return (uint32_t)r.x | ((uint32_t)r.y << 16);
}
__device__ __forceinline__ float2 u2f2(uint32_t u) {
    __half2_raw r; r.x = (unsigned short)(u & 0xFFFFu); r.y = (unsigned short)(u >> 16);
    __half2 h = *reinterpret_cast<__half2*>(&r);
    return __half22float2(h);
}
__device__ __forceinline__ unsigned f2ord(float f) {
    unsigned u = __float_as_uint(f);
    return (u & 0x80000000u) ? ~u : (u | 0x80000000u);
}
__device__ __forceinline__ float ord2f(unsigned u) {
    unsigned b = (u & 0x80000000u) ? (u & 0x7FFFFFFFu) : ~u;
    return __uint_as_float(b);
}
__device__ __forceinline__ float lrelu(float v) { return v > 0.f ? v : 0.2f * v; }

__device__ __forceinline__ void cp16(uint32_t saddr, const void* gptr, bool pred) {
    int sz = pred ? 16 : 0;   // sz=0 -> 16 bytes zero-filled (src-size form)
    asm volatile("cp.async.cg.shared.global [%0], [%1], 16, %2;\n"
                 :: "r"(saddr), "l"(gptr), "r"(sz));
}
__device__ __forceinline__ void cp_commit() {
    asm volatile("cp.async.commit_group;\n" ::: "memory");
}
__device__ __forceinline__ void cp_waitg() {
    asm volatile("cp.async.wait_group %0;\n" :: "n"(GEMM_STAGES - 2) : "memory");
}
__device__ __forceinline__ void ldsm4(uint32_t* r, uint32_t addr) {
    asm volatile("ldmatrix.sync.aligned.m8n8.x4.shared.b16 {%0,%1,%2,%3}, [%4];"
                 : "=r"(r[0]), "=r"(r[1]), "=r"(r[2]), "=r"(r[3]) : "r"(addr));
}

// ---------------------------------------------------------------------------
// init
// ---------------------------------------------------------------------------
__global__ void k_init(float* __restrict__ out, const float* __restrict__ b2, int Nn) {
    size_t total = (size_t)Nn * 30;
    for (size_t i = (size_t)blockIdx.x * blockDim.x + threadIdx.x; i < total;
         i += (size_t)gridDim.x * blockDim.x) {
        if (i < (size_t)Nn) { g_deg[i] = 0; g_sum2[i] = 0.f; g_max2[i] = 0u; }
        if (i < 1024) g_stats[i] = 0.f;
        out[i] = b2[i % 30];
    }
}

// ---------------------------------------------------------------------------
// conversions: x -> fp16 ; W1 -> fp16 transposed [n][k]
// ---------------------------------------------------------------------------
__global__ void k_cvtA(const float* __restrict__ x, size_t n8) {
    const float4* src = (const float4*)x;
    uint4* dst = (uint4*)g_Ah;
    for (size_t i = (size_t)blockIdx.x * blockDim.x + threadIdx.x; i < n8;
         i += (size_t)gridDim.x * blockDim.x) {
        float4 v0 = __ldg(src + 2 * i);
        float4 v1 = __ldg(src + 2 * i + 1);
        uint4 o;
        o.x = h2u(__floats2half2_rn(v0.x, v0.y));
        o.y = h2u(__floats2half2_rn(v0.z, v0.w));
        o.z = h2u(__floats2half2_rn(v1.x, v1.y));
        o.w = h2u(__floats2half2_rn(v1.z, v1.w));
        dst[i] = o;
    }
}

__global__ void k_cvtBT(const float* __restrict__ W1) {
    __shared__ float t[32][33];
    int n0 = blockIdx.x * 32, k0 = blockIdx.y * 32;
    int tx = threadIdx.x, ty = threadIdx.y;   // 32 x 8
#pragma unroll
    for (int i = 0; i < 32; i += 8) {
        int k = k0 + ty + i;
        t[ty + i][tx] = (k < 2000) ? W1[(size_t)k * 2048 + n0 + tx] : 0.f;
    }
    __syncthreads();
#pragma unroll
    for (int i = 0; i < 32; i += 8) {
        int k = k0 + tx;
        if (k < 2000)
            g_W1h[(size_t)(n0 + ty + i) * 2000 + k] = __float2half_rn(t[tx][ty + i]);
    }
}

// ---------------------------------------------------------------------------
// CSR build: degree count -> exclusive scan -> scatter (src indices)
// ---------------------------------------------------------------------------
__global__ void k_deg(const int* __restrict__ ei, int E, int Nn) {
    int e = blockIdx.x * blockDim.x + threadIdx.x;
    if (e >= E + Nn) return;
    int d = (e < E) ? ei[E + e] : e - E;
    atomicAdd(&g_deg[d], 1);
}

__global__ void k_scan(int Nn) {
    __shared__ int wsum[32];
    __shared__ int carry_s;
    int tid = threadIdx.x;
    if (tid == 0) carry_s = 0;
    __syncthreads();
    int iters = (Nn + 1023) / 1024;
    for (int it = 0; it < iters; it++) {
        int i = it * 1024 + tid;
        int v = (i < Nn) ? g_deg[i] : 0;
        int x = v;
#pragma unroll
        for (int o = 1; o < 32; o <<= 1) {
            int y = __shfl_up_sync(0xffffffffu, x, o);
            if ((tid & 31) >= o) x += y;
        }
        if ((tid & 31) == 31) wsum[tid >> 5] = x;
        __syncthreads();
        if (tid < 32) {
            int w = wsum[tid];
#pragma unroll
            for (int o = 1; o < 32; o <<= 1) {
                int y = __shfl_up_sync(0xffffffffu, w, o);
                if (tid >= o) w += y;
            }
            wsum[tid] = w;
        }
        __syncthreads();
        int warp = tid >> 5;
        int incl = x + (warp ? wsum[warp - 1] : 0);
        int excl = incl - v;
        int c = carry_s;
        if (i < Nn) { g_rowptr[i] = c + excl; g_woff[i] = c + excl; }
        __syncthreads();
        if (tid == 1023) carry_s = c + incl;
        __syncthreads();
    }
    if (tid == 0) g_rowptr[Nn] = carry_s;
}

__global__ void k_scatter(const int* __restrict__ ei, int E, int Nn) {
    int e = blockIdx.x * blockDim.x + threadIdx.x;
    if (e >= E + Nn) return;
    int s, d;
    if (e < E) { s = ei[e]; d = ei[E + e]; } else { s = d = e - E; }
    int pos = atomicAdd(&g_woff[d], 1);
    g_csr_src[pos] = s;
}

// ---------------------------------------------------------------------------
// GEMM1: g_H1h[M,2048] = Ah[M,2000] @ W1h^T  (fp16 mma.m16n8k16, f32 accum,
// fp16 output). BM=128 BN=128 BK=32, 256 thr, 4-stage cp.async, ldmatrix.x4.
// ---------------------------------------------------------------------------
__global__ __launch_bounds__(256, 2)
void k_gemm1h(int M) {
    extern __shared__ char smem[];
    const uint32_t sb = (uint32_t)__cvta_generic_to_shared(smem);
    const __half* A = g_Ah;
    const __half* B = g_W1h;

    const int tid  = threadIdx.x;
    const int lane = tid & 31, warp = tid >> 5;
    const int gid  = lane >> 2, tig = lane & 3;
    const int wm   = warp >> 1, wn = warp & 1;
    const int rowBase = blockIdx.y * 128;
    const int colBase = blockIdx.x * 128;
    const int KITERS = 63;   // ceil(2000/32); tail chunks zero-filled by cp.async

    const int mrow = (lane & 7) + ((lane >> 3) & 1) * 8;
    const int koff = ((lane >> 4) & 1) * 16;

    float acc[2][8][4];
#pragma unroll
    for (int i = 0; i < 2; i++)
#pragma unroll
        for (int j = 0; j < 8; j++)
#pragma unroll
            for (int k = 0; k < 4; k++) acc[i][j][k] = 0.f;

    auto load_tile = [&](int st, int k0) {
        uint32_t aBase = sb + st * STAGE_BYTES;
        uint32_t bBase = aBase + OP_TILE;
#pragma unroll
        for (int i = 0; i < 2; i++) {
            int idx = tid + i * 256;
            int r = idx >> 2, j = idx & 3;
            int gr = rowBase + r;
            bool p = (gr < M) && (k0 + j * 8 < 2000);
            cp16(aBase + r * ROW_BYTES + j * 16, A + (size_t)gr * 2000 + k0 + j * 8, p);
        }
#pragma unroll
        for (int i = 0; i < 2; i++) {
            int idx = tid + i * 256;
            int r = idx >> 2, j = idx & 3;
            bool p = (k0 + j * 8 < 2000);
            cp16(bBase + r * ROW_BYTES + j * 16,
                 B + (size_t)(colBase + r) * 2000 + k0 + j * 8, p);
        }
    };

#pragma unroll
    for (int s = 0; s < GEMM_STAGES - 1; s++) {
        load_tile(s, s * 32);
        cp_commit();
    }

    for (int it = 0; it < KITERS; it++) {
        cp_waitg();
        __syncthreads();
        int st = it & (GEMM_STAGES - 1);
        uint32_t aBase = sb + st * STAGE_BYTES;
        uint32_t bBase = aBase + OP_TILE;
#pragma unroll
        for (int ks = 0; ks < 2; ks++) {
            uint32_t a[2][4], bf[4][4];
#pragma unroll
            for (int tm = 0; tm < 2; tm++) {
                uint32_t addr = aBase + (wm * 32 + tm * 16 + mrow) * ROW_BYTES
                              + ks * 32 + koff;
                ldsm4(a[tm], addr);
            }
#pragma unroll
            for (int tp = 0; tp < 4; tp++) {
                uint32_t addr = bBase + (wn * 64 + tp * 16 + mrow) * ROW_BYTES
                              + ks * 32 + koff;
                ldsm4(bf[tp], addr);
            }
#pragma unroll
            for (int tm = 0; tm < 2; tm++)
#pragma unroll
                for (int tp = 0; tp < 4; tp++) {
                    asm volatile(
                        "mma.sync.aligned.m16n8k16.row.col.f32.f16.f16.f32 "
                        "{%0,%1,%2,%3},{%4,%5,%6,%7},{%8,%9},{%0,%1,%2,%3};\n"
                        : "+f"(acc[tm][tp * 2][0]), "+f"(acc[tm][tp * 2][1]),
                          "+f"(acc[tm][tp * 2][2]), "+f"(acc[tm][tp * 2][3])
                        : "r"(a[tm][0]), "r"(a[tm][1]), "r"(a[tm][2]), "r"(a[tm][3]),
                          "r"(bf[tp][0]), "r"(bf[tp][2]));
                    asm volatile(
                        "mma.sync.aligned.m16n8k16.row.col.f32.f16.f16.f32 "
                        "{%0,%1,%2,%3},{%4,%5,%6,%7},{%8,%9},{%0,%1,%2,%3};\n"
                        : "+f"(acc[tm][tp * 2 + 1][0]), "+f"(acc[tm][tp * 2 + 1][1]),
                          "+f"(acc[tm][tp * 2 + 1][2]), "+f"(acc[tm][tp * 2 + 1][3])
                        : "r"(a[tm][0]), "r"(a[tm][1]), "r"(a[tm][2]), "r"(a[tm][3]),
                          "r"(bf[tp][1]), "r"(bf[tp][3]));
                }
        }
        int nit = it + GEMM_STAGES - 1;
        if (nit < KITERS) load_tile(nit & (GEMM_STAGES - 1), nit * 32);
        cp_commit();
    }

    // epilogue: fp16 output. c0,c1 -> (row gid, cols 2tig..+1); c2,c3 -> row gid+8
#pragma unroll
    for (int tm = 0; tm < 2; tm++) {
        int r0 = rowBase + wm * 32 + tm * 16 + gid;
#pragma unroll
        for (int tn = 0; tn < 8; tn++) {
            int c = colBase + wn * 64 + tn * 8 + tig * 2;
            uint32_t p01 = h2u(__floats2half2_rn(acc[tm][tn][0], acc[tm][tn][1]));
            uint32_t p23 = h2u(__floats2half2_rn(acc[tm][tn][2], acc[tm][tn][3]));
            if (r0 < M)
                *(uint32_t*)(g_H1h + (size_t)r0 * 2048 + c) = p01;
            if (r0 + 8 < M)
                *(uint32_t*)(g_H1h + (size_t)(r0 + 8) * 2048 + c) = p23;
        }
    }
}

// ---------------------------------------------------------------------------
// attention dots layer 1: a_src/a_dst[n,h] = <H1[n,h,:], att[h,:]>  (fp16 H1)
// ---------------------------------------------------------------------------
__global__ void k_att1(const float* __restrict__ att_src, const float* __restrict__ att_dst,
                       int Nn) {
    int gw = (int)(((size_t)blockIdx.x * blockDim.x + threadIdx.x) >> 5);
    int lane = threadIdx.x & 31;
    if (gw >= Nn * 4) return;
    int n = gw >> 2, h = gw & 3;
    const uint4* r4 = (const uint4*)(g_H1h + (size_t)n * 2048 + h * 512);   // 64 x 8 halfs
    const float4* s4 = (const float4*)(att_src + h * 512);
    const float4* d4 = (const float4*)(att_dst + h * 512);
    float ss = 0.f, dd = 0.f;
#pragma unroll 2
    for (int i = lane; i < 64; i += 32) {
        uint4 v = __ldg(r4 + i);
        float2 f0 = u2f2(v.x), f1 = u2f2(v.y), f2 = u2f2(v.z), f3 = u2f2(v.w);
        float4 a0 = s4[2 * i], a1 = s4[2 * i + 1];
        float4 b0 = d4[2 * i], b1 = d4[2 * i + 1];
        ss += f0.x * a0.x + f0.y * a0.y + f1.x * a0.z + f1.y * a0.w
            + f2.x * a1.x + f2.y * a1.y + f3.x * a1.z + f3.y * a1.w;
        dd += f0.x * b0.x + f0.y * b0.y + f1.x * b0.z + f1.y * b0.w
            + f2.x * b1.x + f2.y * b1.y + f3.x * b1.z + f3.y * b1.w;
    }
#pragma unroll
    for (int off = 16; off; off >>= 1) {
        ss += __shfl_down_sync(0xffffffffu, ss, off);
        dd += __shfl_down_sync(0xffffffffu, dd, off);
    }
    if (lane == 0) { g_asrc1[gw] = ss; g_adst1[gw] = dd; }
}

// ---------------------------------------------------------------------------
// fused layer-1 softmax + aggregation: one block (256 thr) per destination.
// H1 gathered in fp16 (half the DRAM traffic of f32).
// ---------------------------------------------------------------------------
__global__ __launch_bounds__(256)
void k_agg1(int Nn) {
    const int d = blockIdx.x;
    const int tid = threadIdx.x, lane = tid & 31, warp = tid >> 5;
    const int beg = g_rowptr[d], end = g_rowptr[d + 1];

    __shared__ float4 rwarp[8];
    __shared__ float4 rbc;
    __shared__ int    ssrc[256];
    __shared__ float4 sal[256];

    float4 ad = *(const float4*)(g_adst1 + (size_t)d * 4);
    const float NEGINF = __int_as_float(0xff800000);

    float4 mx = make_float4(NEGINF, NEGINF, NEGINF, NEGINF);
    for (int j = beg + tid; j < end; j += 256) {
        int s = g_csr_src[j];
        float4 as = *(const float4*)(g_asrc1 + (size_t)s * 4);
        mx.x = fmaxf(mx.x, lrelu(as.x + ad.x));
        mx.y = fmaxf(mx.y, lrelu(as.y + ad.y));
        mx.z = fmaxf(mx.z, lrelu(as.z + ad.z));
        mx.w = fmaxf(mx.w, lrelu(as.w + ad.w));
    }
#pragma unroll
    for (int o = 16; o; o >>= 1) {
        mx.x = fmaxf(mx.x, __shfl_down_sync(0xffffffffu, mx.x, o));
        mx.y = fmaxf(mx.y, __shfl_down_sync(0xffffffffu, mx.y, o));
        mx.z = fmaxf(mx.z, __shfl_down_sync(0xffffffffu, mx.z, o));
        mx.w = fmaxf(mx.w, __shfl_down_sync(0xffffffffu, mx.w, o));
    }
    if (lane == 0) rwarp[warp] = mx;
    __syncthreads();
    if (tid == 0) {
        float4 m = rwarp[0];
#pragma unroll
        for (int w = 1; w < 8; w++) {
            m.x = fmaxf(m.x, rwarp[w].x); m.y = fmaxf(m.y, rwarp[w].y);
            m.z = fmaxf(m.z, rwarp[w].z); m.w = fmaxf(m.w, rwarp[w].w);
        }
        rbc = m;
    }
    __syncthreads();
    mx = rbc;

    float4 sm = make_float4(0.f, 0.f, 0.f, 0.f);
    for (int j = beg + tid; j < end; j += 256) {
        int s = g_csr_src[j];
        float4 as = *(const float4*)(g_asrc1 + (size_t)s * 4);
        sm.x += expf(lrelu(as.x + ad.x) - mx.x);
        sm.y += expf(lrelu(as.y + ad.y) - mx.y);
        sm.z += expf(lrelu(as.z + ad.z) - mx.z);
        sm.w += expf(lrelu(as.w + ad.w) - mx.w);
    }
#pragma unroll
    for (int o = 16; o; o >>= 1) {
        sm.x += __shfl_down_sync(0xffffffffu, sm.x, o);
        sm.y += __shfl_down_sync(0xffffffffu, sm.y, o);
        sm.z += __shfl_down_sync(0xffffffffu, sm.z, o);
        sm.w += __shfl_down_sync(0xffffffffu, sm.w, o);
    }
    if (lane == 0) rwarp[warp] = sm;
    __syncthreads();
    if (tid == 0) {
        float4 t = rwarp[0];
#pragma unroll
        for (int w = 1; w < 8; w++) {
            t.x += rwarp[w].x; t.y += rwarp[w].y; t.z += rwarp[w].z; t.w += rwarp[w].w;
        }
        rbc = t;
    }
    __syncthreads();
    sm = rbc;
    float4 inv;
    inv.x = 0.25f / (sm.x + 1e-16f);
    inv.y = 0.25f / (sm.y + 1e-16f);
    inv.z = 0.25f / (sm.z + 1e-16f);
    inv.w = 0.25f / (sm.w + 1e-16f);

    float2 acc = make_float2(0.f, 0.f);
    for (int c0 = beg; c0 < end; c0 += 256) {
        int cnt = min(end - c0, 256);
        __syncthreads();
        if (tid < cnt) {
            int s = g_csr_src[c0 + tid];
            float4 as = *(const float4*)(g_asrc1 + (size_t)s * 4);
            float4 al;
            al.x = expf(lrelu(as.x + ad.x) - mx.x) * inv.x;
            al.y = expf(lrelu(as.y + ad.y) - mx.y) * inv.y;
            al.z = expf(lrelu(as.z + ad.z) - mx.z) * inv.z;
            al.w = expf(lrelu(as.w + ad.w) - mx.w) * inv.w;
            ssrc[tid] = s;
            sal[tid] = al;
        }
        __syncthreads();
        for (int jj = 0; jj < cnt; jj++) {
            const __half* h = g_H1h + (size_t)ssrc[jj] * 2048 + 2 * tid;
            float4 al = sal[jj];
            float2 v0 = u2f2(__ldg((const uint32_t*)(h)));
            float2 v1 = u2f2(__ldg((const uint32_t*)(h + 512)));
            float2 v2 = u2f2(__ldg((const uint32_t*)(h + 1024)));
            float2 v3 = u2f2(__ldg((const uint32_t*)(h + 1536)));
            acc.x += al.x * v0.x + al.y * v1.x + al.z * v2.x + al.w * v3.x;
            acc.y += al.x * v0.y + al.y * v1.y + al.z * v2.y + al.w * v3.y;
        }
    }
    *(float2*)(g_out1 + (size_t)d * 512 + 2 * tid) = acc;
}

// ---------------------------------------------------------------------------
// BatchNorm stats (b1 BN-invariant -> skipped) + normalize + ELU
// ---------------------------------------------------------------------------
__global__ void k_bnstats(int Nn) {
    int c = blockIdx.x * blockDim.x + threadIdx.x;   // 0..511
    int r0 = blockIdx.y * 64;
    int r1 = min(r0 + 64, Nn);
    float s1 = 0.f, s2 = 0.f;
    for (int r = r0; r < r1; r++) {
        float v = g_out1[(size_t)r * 512 + c];
        s1 += v;
        s2 = fmaf(v, v, s2);
    }
    atomicAdd(&g_stats[c], s1);
    atomicAdd(&g_stats[512 + c], s2);
}

__global__ void k_bnelu(const float* __restrict__ gamma, const float* __restrict__ beta,
                        int Nn, float invN) {
    size_t total = (size_t)Nn * 512;
    for (size_t i = (size_t)blockIdx.x * blockDim.x + threadIdx.x; i < total;
         i += (size_t)gridDim.x * blockDim.x) {
        int c = (int)(i & 511);
        float mu = g_stats[c] * invN;
        float var = g_stats[512 + c] * invN - mu * mu;
        float x = (g_out1[i] - mu) * rsqrtf(var + 1e-5f) * gamma[c] + beta[c];
        g_hmid[i] = x > 0.f ? x : expm1f(x);
    }
}

// ---------------------------------------------------------------------------
// layer-2 prep: H2 = hmid @ W2 (one warp per row) + attention scalars
// ---------------------------------------------------------------------------
__global__ void k_l2prep(const float* __restrict__ W2, const float* __restrict__ as2,
                         const float* __restrict__ ad2, int Nn) {
    int gw = (int)(((size_t)blockIdx.x * blockDim.x + threadIdx.x) >> 5);
    int lane = threadIdx.x & 31;
    if (gw >= Nn) return;
    const float* h = g_hmid + (size_t)gw * 512;
    float acc = 0.f;
    for (int kb = 0; kb < 16; kb++) {
        float hv = h[kb * 32 + lane];
#pragma unroll
        for (int j = 0; j < 32; j++) {
            float hk = __shfl_sync(0xffffffffu, hv, j);
            float w = (lane < 30) ? __ldg(W2 + (size_t)(kb * 32 + j) * 30 + lane) : 0.f;
            acc = fmaf(hk, w, acc);
        }
    }
    float sa = (lane < 30) ? acc * __ldg(as2 + lane) : 0.f;
    float sd = (lane < 30) ? acc * __ldg(ad2 + lane) : 0.f;
#pragma unroll
    for (int off = 16; off; off >>= 1) {
        sa += __shfl_down_sync(0xffffffffu, sa, off);
        sd += __shfl_down_sync(0xffffffffu, sd, off);
    }
    if (lane < 30) g_H2[(size_t)gw * 30 + lane] = acc;
    if (lane == 0) { g_asrc2[gw] = sa; g_adst2[gw] = sd; }
}

// ---------------------------------------------------------------------------
// layer-2 edge passes (H=1, C=30)
// ---------------------------------------------------------------------------
__global__ void k_edge_max2(const int* __restrict__ ei, int E, int Nn) {
    int e = blockIdx.x * blockDim.x + threadIdx.x;
    if (e >= E + Nn) return;
    int s, d;
    if (e < E) { s = ei[e]; d = ei[E + e]; } else { s = d = e - E; }
    float v = lrelu(g_asrc2[s] + g_adst2[d]);
    g_e2[e] = v;
    atomicMax(&g_max2[d], f2ord(v));
}

__global__ void k_exp2(const int* __restrict__ ei, int E, int Nn) {
    int e = blockIdx.x * blockDim.x + threadIdx.x;
    if (e >= E + Nn) return;
    int d = (e < E) ? ei[E + e] : e - E;
    float ex = expf(g_e2[e] - ord2f(g_max2[d]));
    g_e2[e] = ex;
    atomicAdd(&g_sum2[d], ex);
}

__global__ void k_msg2(const int* __restrict__ ei, int E, int Nn, float* __restrict__ out) {
    int gw = (int)(((size_t)blockIdx.x * blockDim.x + threadIdx.x) >> 5);
    int lane = threadIdx.x & 31;
    if (gw >= E + Nn) return;
    int s, d;
    if (gw < E) { s = ei[gw]; d = ei[E + gw]; } else { s = d = gw - E; }
    float al = g_e2[gw] / (g_sum2[d] + 1e-16f);
    if (lane < 30)
        atomicAdd(out + (size_t)d * 30 + lane, al * __ldg(g_H2 + (size_t)s * 30 + lane));
}

// ---------------------------------------------------------------------------
// launch
// ---------------------------------------------------------------------------
extern "C" void kernel_launch(void* const* d_in, const int* in_sizes, int n_in,
                              void* d_out, int out_size) {
    const float* x       = (const float*)d_in[0];
    const int*   ei      = (const int*)d_in[1];
    const float* W1      = (const float*)d_in[2];
    const float* attsrc1 = (const float*)d_in[3];
    const float* attdst1 = (const float*)d_in[4];
    // d_in[5] = b1: BN-invariant, skipped
    const float* gamma   = (const float*)d_in[6];
    const float* beta    = (const float*)d_in[7];
    const float* W2      = (const float*)d_in[8];
    const float* attsrc2 = (const float*)d_in[9];
    const float* attdst2 = (const float*)d_in[10];
    const float* b2      = (const float*)d_in[11];
    float* out = (float*)d_out;

    int Nn = in_sizes[0] / 2000;
    int E  = in_sizes[1] / 2;
    int Etot = E + Nn;
    int eb = (Etot + 255) / 256;

    cudaFuncSetAttribute(k_gemm1h, cudaFuncAttributeMaxDynamicSharedMemorySize, SMEM_GEMM);

    k_init<<<2048, 256>>>(out, b2, Nn);
    k_cvtA<<<2048, 256>>>(x, (size_t)Nn * 2000 / 8);
    k_cvtBT<<<dim3(64, 63), dim3(32, 8)>>>(W1);
    k_deg<<<eb, 256>>>(ei, E, Nn);
    k_scan<<<1, 1024>>>(Nn);
    k_scatter<<<eb, 256>>>(ei, E, Nn);

    dim3 g1(16, (Nn + 127) / 128);   // x = col tiles (share A rows in L2)
    k_gemm1h<<<g1, 256, SMEM_GEMM>>>(Nn);

    k_att1<<<(Nn * 4 * 32 + 255) / 256, 256>>>(attsrc1, attdst1, Nn);

    k_agg1<<<Nn, 256>>>(Nn);

    dim3 gs(2, (Nn + 63) / 64);
    k_bnstats<<<gs, 256>>>(Nn);
    k_bnelu<<<4096, 256>>>(gamma, beta, Nn, 1.f / (float)Nn);

    k_l2prep<<<(int)(((size_t)Nn * 32 + 255) / 256), 256>>>(W2, attsrc2, attdst2, Nn);

    k_edge_max2<<<eb, 256>>>(ei, E, Nn);
    k_exp2<<<eb, 256>>>(ei, E, Nn);
    int mb = (int)(((size_t)Etot * 32 + 255) / 256);
    k_msg2<<<mb, 256>>>(ei, E, Nn, out);
}

// round 14
// speedup vs baseline: 1.5612x; 1.0498x over previous
#include <cuda_runtime.h>
#include <cuda_fp16.h>
#include <cstdint>
#include <cstddef>

// ---------------------------------------------------------------------------
// GATEncoder: GATConv(2000->4x512, mean heads) -> BN -> ELU -> GATConv(512->30)
// N=50000, F=2000, H=4, C=512, LAT=30, E=800000 (+N self loops)
// R14: layer-2 edge phase CSR-fused into one warp-per-dst kernel (no e2
//      buffer, no atomics, out written once with b2 folded in); BN+ELU fused
//      into l2prep (g_hmid eliminated). GEMM1/agg1 unchanged from 2703us R13.
// ---------------------------------------------------------------------------

#define NMAX 50000
#define EMAX 800000
#define ETMAX (EMAX + NMAX)

#define GEMM_STAGES 4
#define ROW_BYTES 80                       // 32 halfs (64B) + 16B pad: LDSM conflict-free
#define OP_TILE (128 * ROW_BYTES)          // 10240 B per operand per stage
#define STAGE_BYTES (2 * OP_TILE)          // 20480
#define SMEM_GEMM (GEMM_STAGES * STAGE_BYTES)   // 81920

// ---- device scratch (static; no runtime allocation allowed) ----
__device__ __half   g_H1h[(size_t)NMAX * 2048];   // x @ W1 in fp16
__device__ __half   g_Ah[(size_t)NMAX * 2000];    // x in fp16
__device__ __half   g_W1h[(size_t)2048 * 2000];   // W1^T in fp16 ([n][k])
__device__ float    g_out1[(size_t)NMAX * 512];   // layer-1 aggregate
__device__ float    g_H2[(size_t)NMAX * 30];      // ELU(BN(out1)) @ W2
__device__ float    g_asrc1[NMAX * 4];
__device__ float    g_adst1[NMAX * 4];
__device__ float    g_asrc2[NMAX];
__device__ float    g_adst2[NMAX];
__device__ float    g_stats[1024];                // [0:512) sum, [512:1024) sumsq
// CSR by destination
__device__ int      g_deg[NMAX];
__device__ int      g_rowptr[NMAX + 1];
__device__ int      g_woff[NMAX];
__device__ int      g_csr_src[ETMAX];

// ---- helpers ----
__device__ __forceinline__ uint32_t h2u(__half2 h) {
    __half2_raw r = *reinterpret_cast<__half2_raw*>(&h);
    return (uint32_t)r.x | ((uint32_t)r.y << 16);
}
__device__ __forceinline__ float2 u2f2(uint32_t u) {
    __half2_raw r; r.x = (unsigned short)(u & 0xFFFFu); r.y = (unsigned short)(u >> 16);
    __half2 h = *reinterpret_cast<__half2*>(&r);
    return __half22float2(h);
}
__device__ __forceinline__ float lrelu(float v) { return v > 0.f ? v : 0.2f * v; }

__device__ __forceinline__ void cp16(uint32_t saddr, const void* gptr, bool pred) {
    int sz = pred ? 16 : 0;   // sz=0 -> 16 bytes zero-filled (src-size form)
    asm volatile("cp.async.cg.shared.global [%0], [%1], 16, %2;\n"
                 :: "r"(saddr), "l"(gptr), "r"(sz));
}
__device__ __forceinline__ void cp_commit() {
    asm volatile("cp.async.commit_group;\n" ::: "memory");
}
__device__ __forceinline__ void cp_waitg() {
    asm volatile("cp.async.wait_group %0;\n" :: "n"(GEMM_STAGES - 2) : "memory");
}
__device__ __forceinline__ void ldsm4(uint32_t* r, uint32_t addr) {
    asm volatile("ldmatrix.sync.aligned.m8n8.x4.shared.b16 {%0,%1,%2,%3}, [%4];"
                 : "=r"(r[0]), "=r"(r[1]), "=r"(r[2]), "=r"(r[3]) : "r"(addr));
}

// ---------------------------------------------------------------------------
// init: zero CSR degree + BN stats
// ---------------------------------------------------------------------------
__global__ void k_init(int Nn) {
    for (int i = blockIdx.x * blockDim.x + threadIdx.x; i < Nn;
         i += gridDim.x * blockDim.x) {
        g_deg[i] = 0;
        if (i < 1024) g_stats[i] = 0.f;
    }
}

// ---------------------------------------------------------------------------
// conversions: x -> fp16 ; W1 -> fp16 transposed [n][k]
// ---------------------------------------------------------------------------
__global__ void k_cvtA(const float* __restrict__ x, size_t n8) {
    const float4* src = (const float4*)x;
    uint4* dst = (uint4*)g_Ah;
    for (size_t i = (size_t)blockIdx.x * blockDim.x + threadIdx.x; i < n8;
         i += (size_t)gridDim.x * blockDim.x) {
        float4 v0 = __ldg(src + 2 * i);
        float4 v1 = __ldg(src + 2 * i + 1);
        uint4 o;
        o.x = h2u(__floats2half2_rn(v0.x, v0.y));
        o.y = h2u(__floats2half2_rn(v0.z, v0.w));
        o.z = h2u(__floats2half2_rn(v1.x, v1.y));
        o.w = h2u(__floats2half2_rn(v1.z, v1.w));
        dst[i] = o;
    }
}

__global__ void k_cvtBT(const float* __restrict__ W1) {
    __shared__ float t[32][33];
    int n0 = blockIdx.x * 32, k0 = blockIdx.y * 32;
    int tx = threadIdx.x, ty = threadIdx.y;   // 32 x 8
#pragma unroll
    for (int i = 0; i < 32; i += 8) {
        int k = k0 + ty + i;
        t[ty + i][tx] = (k < 2000) ? W1[(size_t)k * 2048 + n0 + tx] : 0.f;
    }
    __syncthreads();
#pragma unroll
    for (int i = 0; i < 32; i += 8) {
        int k = k0 + tx;
        if (k < 2000)
            g_W1h[(size_t)(n0 + ty + i) * 2000 + k] = __float2half_rn(t[tx][ty + i]);
    }
}

// ---------------------------------------------------------------------------
// CSR build: degree count -> exclusive scan -> scatter (src indices)
// ---------------------------------------------------------------------------
__global__ void k_deg(const int* __restrict__ ei, int E, int Nn) {
    int e = blockIdx.x * blockDim.x + threadIdx.x;
    if (e >= E + Nn) return;
    int d = (e < E) ? ei[E + e] : e - E;
    atomicAdd(&g_deg[d], 1);
}

__global__ void k_scan(int Nn) {
    __shared__ int wsum[32];
    __shared__ int carry_s;
    int tid = threadIdx.x;
    if (tid == 0) carry_s = 0;
    __syncthreads();
    int iters = (Nn + 1023) / 1024;
    for (int it = 0; it < iters; it++) {
        int i = it * 1024 + tid;
        int v = (i < Nn) ? g_deg[i] : 0;
        int x = v;
#pragma unroll
        for (int o = 1; o < 32; o <<= 1) {
            int y = __shfl_up_sync(0xffffffffu, x, o);
            if ((tid & 31) >= o) x += y;
        }
        if ((tid & 31) == 31) wsum[tid >> 5] = x;
        __syncthreads();
        if (tid < 32) {
            int w = wsum[tid];
#pragma unroll
            for (int o = 1; o < 32; o <<= 1) {
                int y = __shfl_up_sync(0xffffffffu, w, o);
                if (tid >= o) w += y;
            }
            wsum[tid] = w;
        }
        __syncthreads();
        int warp = tid >> 5;
        int incl = x + (warp ? wsum[warp - 1] : 0);
        int excl = incl - v;
        int c = carry_s;
        if (i < Nn) { g_rowptr[i] = c + excl; g_woff[i] = c + excl; }
        __syncthreads();
        if (tid == 1023) carry_s = c + incl;
        __syncthreads();
    }
    if (tid == 0) g_rowptr[Nn] = carry_s;
}

__global__ void k_scatter(const int* __restrict__ ei, int E, int Nn) {
    int e = blockIdx.x * blockDim.x + threadIdx.x;
    if (e >= E + Nn) return;
    int s, d;
    if (e < E) { s = ei[e]; d = ei[E + e]; } else { s = d = e - E; }
    int pos = atomicAdd(&g_woff[d], 1);
    g_csr_src[pos] = s;
}

// ---------------------------------------------------------------------------
// GEMM1: g_H1h[M,2048] = Ah[M,2000] @ W1h^T  (fp16 mma.m16n8k16, f32 accum,
// fp16 output). BM=128 BN=128 BK=32, 256 thr, 4-stage cp.async, ldmatrix.x4.
// ---------------------------------------------------------------------------
__global__ __launch_bounds__(256, 2)
void k_gemm1h(int M) {
    extern __shared__ char smem[];
    const uint32_t sb = (uint32_t)__cvta_generic_to_shared(smem);
    const __half* A = g_Ah;
    const __half* B = g_W1h;

    const int tid  = threadIdx.x;
    const int lane = tid & 31, warp = tid >> 5;
    const int gid  = lane >> 2, tig = lane & 3;
    const int wm   = warp >> 1, wn = warp & 1;
    const int rowBase = blockIdx.y * 128;
    const int colBase = blockIdx.x * 128;
    const int KITERS = 63;   // ceil(2000/32); tail chunks zero-filled by cp.async

    const int mrow = (lane & 7) + ((lane >> 3) & 1) * 8;
    const int koff = ((lane >> 4) & 1) * 16;

    float acc[2][8][4];
#pragma unroll
    for (int i = 0; i < 2; i++)
#pragma unroll
        for (int j = 0; j < 8; j++)
#pragma unroll
            for (int k = 0; k < 4; k++) acc[i][j][k] = 0.f;

    auto load_tile = [&](int st, int k0) {
        uint32_t aBase = sb + st * STAGE_BYTES;
        uint32_t bBase = aBase + OP_TILE;
#pragma unroll
        for (int i = 0; i < 2; i++) {
            int idx = tid + i * 256;
            int r = idx >> 2, j = idx & 3;
            int gr = rowBase + r;
            bool p = (gr < M) && (k0 + j * 8 < 2000);
            cp16(aBase + r * ROW_BYTES + j * 16, A + (size_t)gr * 2000 + k0 + j * 8, p);
        }
#pragma unroll
        for (int i = 0; i < 2; i++) {
            int idx = tid + i * 256;
            int r = idx >> 2, j = idx & 3;
            bool p = (k0 + j * 8 < 2000);
            cp16(bBase + r * ROW_BYTES + j * 16,
                 B + (size_t)(colBase + r) * 2000 + k0 + j * 8, p);
        }
    };

#pragma unroll
    for (int s = 0; s < GEMM_STAGES - 1; s++) {
        load_tile(s, s * 32);
        cp_commit();
    }

    for (int it = 0; it < KITERS; it++) {
        cp_waitg();
        __syncthreads();
        int st = it & (GEMM_STAGES - 1);
        uint32_t aBase = sb + st * STAGE_BYTES;
        uint32_t bBase = aBase + OP_TILE;
#pragma unroll
        for (int ks = 0; ks < 2; ks++) {
            uint32_t a[2][4], bf[4][4];
#pragma unroll
            for (int tm = 0; tm < 2; tm++) {
                uint32_t addr = aBase + (wm * 32 + tm * 16 + mrow) * ROW_BYTES
                              + ks * 32 + koff;
                ldsm4(a[tm], addr);
            }
#pragma unroll
            for (int tp = 0; tp < 4; tp++) {
                uint32_t addr = bBase + (wn * 64 + tp * 16 + mrow) * ROW_BYTES
                              + ks * 32 + koff;
                ldsm4(bf[tp], addr);
            }
#pragma unroll
            for (int tm = 0; tm < 2; tm++)
#pragma unroll
                for (int tp = 0; tp < 4; tp++) {
                    asm volatile(
                        "mma.sync.aligned.m16n8k16.row.col.f32.f16.f16.f32 "
                        "{%0,%1,%2,%3},{%4,%5,%6,%7},{%8,%9},{%0,%1,%2,%3};\n"
                        : "+f"(acc[tm][tp * 2][0]), "+f"(acc[tm][tp * 2][1]),
                          "+f"(acc[tm][tp * 2][2]), "+f"(acc[tm][tp * 2][3])
                        : "r"(a[tm][0]), "r"(a[tm][1]), "r"(a[tm][2]), "r"(a[tm][3]),
                          "r"(bf[tp][0]), "r"(bf[tp][2]));
                    asm volatile(
                        "mma.sync.aligned.m16n8k16.row.col.f32.f16.f16.f32 "
                        "{%0,%1,%2,%3},{%4,%5,%6,%7},{%8,%9},{%0,%1,%2,%3};\n"
                        : "+f"(acc[tm][tp * 2 + 1][0]), "+f"(acc[tm][tp * 2 + 1][1]),
                          "+f"(acc[tm][tp * 2 + 1][2]), "+f"(acc[tm][tp * 2 + 1][3])
                        : "r"(a[tm][0]), "r"(a[tm][1]), "r"(a[tm][2]), "r"(a[tm][3]),
                          "r"(bf[tp][1]), "r"(bf[tp][3]));
                }
        }
        int nit = it + GEMM_STAGES - 1;
        if (nit < KITERS) load_tile(nit & (GEMM_STAGES - 1), nit * 32);
        cp_commit();
    }

    // epilogue: fp16 output
#pragma unroll
    for (int tm = 0; tm < 2; tm++) {
        int r0 = rowBase + wm * 32 + tm * 16 + gid;
#pragma unroll
        for (int tn = 0; tn < 8; tn++) {
            int c = colBase + wn * 64 + tn * 8 + tig * 2;
            uint32_t p01 = h2u(__floats2half2_rn(acc[tm][tn][0], acc[tm][tn][1]));
            uint32_t p23 = h2u(__floats2half2_rn(acc[tm][tn][2], acc[tm][tn][3]));
            if (r0 < M)
                *(uint32_t*)(g_H1h + (size_t)r0 * 2048 + c) = p01;
            if (r0 + 8 < M)
                *(uint32_t*)(g_H1h + (size_t)(r0 + 8) * 2048 + c) = p23;
        }
    }
}

// ---------------------------------------------------------------------------
// attention dots layer 1: a_src/a_dst[n,h] = <H1[n,h,:], att[h,:]>  (fp16 H1)
// ---------------------------------------------------------------------------
__global__ void k_att1(const float* __restrict__ att_src, const float* __restrict__ att_dst,
                       int Nn) {
    int gw = (int)(((size_t)blockIdx.x * blockDim.x + threadIdx.x) >> 5);
    int lane = threadIdx.x & 31;
    if (gw >= Nn * 4) return;
    int n = gw >> 2, h = gw & 3;
    const uint4* r4 = (const uint4*)(g_H1h + (size_t)n * 2048 + h * 512);   // 64 x 8 halfs
    const float4* s4 = (const float4*)(att_src + h * 512);
    const float4* d4 = (const float4*)(att_dst + h * 512);
    float ss = 0.f, dd = 0.f;
#pragma unroll 2
    for (int i = lane; i < 64; i += 32) {
        uint4 v = __ldg(r4 + i);
        float2 f0 = u2f2(v.x), f1 = u2f2(v.y), f2 = u2f2(v.z), f3 = u2f2(v.w);
        float4 a0 = s4[2 * i], a1 = s4[2 * i + 1];
        float4 b0 = d4[2 * i], b1 = d4[2 * i + 1];
        ss += f0.x * a0.x + f0.y * a0.y + f1.x * a0.z + f1.y * a0.w
            + f2.x * a1.x + f2.y * a1.y + f3.x * a1.z + f3.y * a1.w;
        dd += f0.x * b0.x + f0.y * b0.y + f1.x * b0.z + f1.y * b0.w
            + f2.x * b1.x + f2.y * b1.y + f3.x * b1.z + f3.y * b1.w;
    }
#pragma unroll
    for (int off = 16; off; off >>= 1) {
        ss += __shfl_down_sync(0xffffffffu, ss, off);
        dd += __shfl_down_sync(0xffffffffu, dd, off);
    }
    if (lane == 0) { g_asrc1[gw] = ss; g_adst1[gw] = dd; }
}

// ---------------------------------------------------------------------------
// fused layer-1 softmax + aggregation: one block (256 thr) per destination.
// ---------------------------------------------------------------------------
__global__ __launch_bounds__(256)
void k_agg1(int Nn) {
    const int d = blockIdx.x;
    const int tid = threadIdx.x, lane = tid & 31, warp = tid >> 5;
    const int beg = g_rowptr[d], end = g_rowptr[d + 1];

    __shared__ float4 rwarp[8];
    __shared__ float4 rbc;
    __shared__ int    ssrc[256];
    __shared__ float4 sal[256];

    float4 ad = *(const float4*)(g_adst1 + (size_t)d * 4);
    const float NEGINF = __int_as_float(0xff800000);

    float4 mx = make_float4(NEGINF, NEGINF, NEGINF, NEGINF);
    for (int j = beg + tid; j < end; j += 256) {
        int s = g_csr_src[j];
        float4 as = *(const float4*)(g_asrc1 + (size_t)s * 4);
        mx.x = fmaxf(mx.x, lrelu(as.x + ad.x));
        mx.y = fmaxf(mx.y, lrelu(as.y + ad.y));
        mx.z = fmaxf(mx.z, lrelu(as.z + ad.z));
        mx.w = fmaxf(mx.w, lrelu(as.w + ad.w));
    }
#pragma unroll
    for (int o = 16; o; o >>= 1) {
        mx.x = fmaxf(mx.x, __shfl_down_sync(0xffffffffu, mx.x, o));
        mx.y = fmaxf(mx.y, __shfl_down_sync(0xffffffffu, mx.y, o));
        mx.z = fmaxf(mx.z, __shfl_down_sync(0xffffffffu, mx.z, o));
        mx.w = fmaxf(mx.w, __shfl_down_sync(0xffffffffu, mx.w, o));
    }
    if (lane == 0) rwarp[warp] = mx;
    __syncthreads();
    if (tid == 0) {
        float4 m = rwarp[0];
#pragma unroll
        for (int w = 1; w < 8; w++) {
            m.x = fmaxf(m.x, rwarp[w].x); m.y = fmaxf(m.y, rwarp[w].y);
            m.z = fmaxf(m.z, rwarp[w].z); m.w = fmaxf(m.w, rwarp[w].w);
        }
        rbc = m;
    }
    __syncthreads();
    mx = rbc;

    float4 sm = make_float4(0.f, 0.f, 0.f, 0.f);
    for (int j = beg + tid; j < end; j += 256) {
        int s = g_csr_src[j];
        float4 as = *(const float4*)(g_asrc1 + (size_t)s * 4);
        sm.x += expf(lrelu(as.x + ad.x) - mx.x);
        sm.y += expf(lrelu(as.y + ad.y) - mx.y);
        sm.z += expf(lrelu(as.z + ad.z) - mx.z);
        sm.w += expf(lrelu(as.w + ad.w) - mx.w);
    }
#pragma unroll
    for (int o = 16; o; o >>= 1) {
        sm.x += __shfl_down_sync(0xffffffffu, sm.x, o);
        sm.y += __shfl_down_sync(0xffffffffu, sm.y, o);
        sm.z += __shfl_down_sync(0xffffffffu, sm.z, o);
        sm.w += __shfl_down_sync(0xffffffffu, sm.w, o);
    }
    if (lane == 0) rwarp[warp] = sm;
    __syncthreads();
    if (tid == 0) {
        float4 t = rwarp[0];
#pragma unroll
        for (int w = 1; w < 8; w++) {
            t.x += rwarp[w].x; t.y += rwarp[w].y; t.z += rwarp[w].z; t.w += rwarp[w].w;
        }
        rbc = t;
    }
    __syncthreads();
    sm = rbc;
    float4 inv;
    inv.x = 0.25f / (sm.x + 1e-16f);
    inv.y = 0.25f / (sm.y + 1e-16f);
    inv.z = 0.25f / (sm.z + 1e-16f);
    inv.w = 0.25f / (sm.w + 1e-16f);

    float2 acc = make_float2(0.f, 0.f);
    for (int c0 = beg; c0 < end; c0 += 256) {
        int cnt = min(end - c0, 256);
        __syncthreads();
        if (tid < cnt) {
            int s = g_csr_src[c0 + tid];
            float4 as = *(const float4*)(g_asrc1 + (size_t)s * 4);
            float4 al;
            al.x = expf(lrelu(as.x + ad.x) - mx.x) * inv.x;
            al.y = expf(lrelu(as.y + ad.y) - mx.y) * inv.y;
            al.z = expf(lrelu(as.z + ad.z) - mx.z) * inv.z;
            al.w = expf(lrelu(as.w + ad.w) - mx.w) * inv.w;
            ssrc[tid] = s;
            sal[tid] = al;
        }
        __syncthreads();
        for (int jj = 0; jj < cnt; jj++) {
            const __half* h = g_H1h + (size_t)ssrc[jj] * 2048 + 2 * tid;
            float4 al = sal[jj];
            float2 v0 = u2f2(__ldg((const uint32_t*)(h)));
            float2 v1 = u2f2(__ldg((const uint32_t*)(h + 512)));
            float2 v2 = u2f2(__ldg((const uint32_t*)(h + 1024)));
            float2 v3 = u2f2(__ldg((const uint32_t*)(h + 1536)));
            acc.x += al.x * v0.x + al.y * v1.x + al.z * v2.x + al.w * v3.x;
            acc.y += al.x * v0.y + al.y * v1.y + al.z * v2.y + al.w * v3.y;
        }
    }
    *(float2*)(g_out1 + (size_t)d * 512 + 2 * tid) = acc;
}

// ---------------------------------------------------------------------------
// BatchNorm stats (b1 BN-invariant -> skipped)
// ---------------------------------------------------------------------------
__global__ void k_bnstats(int Nn) {
    int c = blockIdx.x * blockDim.x + threadIdx.x;   // 0..511
    int r0 = blockIdx.y * 64;
    int r1 = min(r0 + 64, Nn);
    float s1 = 0.f, s2 = 0.f;
    for (int r = r0; r < r1; r++) {
        float v = g_out1[(size_t)r * 512 + c];
        s1 += v;
        s2 = fmaf(v, v, s2);
    }
    atomicAdd(&g_stats[c], s1);
    atomicAdd(&g_stats[512 + c], s2);
}

// ---------------------------------------------------------------------------
// layer-2 prep with fused BN+ELU: H2 = ELU(BN(out1)) @ W2 (one warp per row)
// + attention scalars. g_hmid eliminated.
// ---------------------------------------------------------------------------
__global__ void k_l2prep(const float* __restrict__ W2, const float* __restrict__ as2,
                         const float* __restrict__ ad2, const float* __restrict__ gamma,
                         const float* __restrict__ beta, int Nn, float invN) {
    int gw = (int)(((size_t)blockIdx.x * blockDim.x + threadIdx.x) >> 5);
    int lane = threadIdx.x & 31;
    if (gw >= Nn) return;
    const float* h = g_out1 + (size_t)gw * 512;
    float acc = 0.f;
    for (int kb = 0; kb < 16; kb++) {
        int c = kb * 32 + lane;
        float mu = __ldg(g_stats + c) * invN;
        float var = __ldg(g_stats + 512 + c) * invN - mu * mu;
        float scale = rsqrtf(var + 1e-5f) * __ldg(gamma + c);
        float shift = __ldg(beta + c) - mu * scale;
        float xv = h[c] * scale + shift;
        float hv = xv > 0.f ? xv : expm1f(xv);
#pragma unroll
        for (int j = 0; j < 32; j++) {
            float hk = __shfl_sync(0xffffffffu, hv, j);
            float w = (lane < 30) ? __ldg(W2 + (size_t)(kb * 32 + j) * 30 + lane) : 0.f;
            acc = fmaf(hk, w, acc);
        }
    }
    float sa = (lane < 30) ? acc * __ldg(as2 + lane) : 0.f;
    float sd = (lane < 30) ? acc * __ldg(ad2 + lane) : 0.f;
#pragma unroll
    for (int off = 16; off; off >>= 1) {
        sa += __shfl_down_sync(0xffffffffu, sa, off);
        sd += __shfl_down_sync(0xffffffffu, sd, off);
    }
    if (lane < 30) g_H2[(size_t)gw * 30 + lane] = acc;
    if (lane == 0) { g_asrc2[gw] = sa; g_adst2[gw] = sd; }
}

// ---------------------------------------------------------------------------
// fused layer-2 softmax + aggregation: one warp per destination.
// out[d] = b2 + sum_s alpha_s * H2[s]  (no atomics, out written once)
// ---------------------------------------------------------------------------
__global__ __launch_bounds__(256)
void k_l2agg(const float* __restrict__ b2, float* __restrict__ out, int Nn) {
    int gw = (int)(((size_t)blockIdx.x * blockDim.x + threadIdx.x) >> 5);
    int lane = threadIdx.x & 31;
    if (gw >= Nn) return;
    const int d = gw;
    const int beg = g_rowptr[d], end = g_rowptr[d + 1];
    const float adv = g_adst2[d];
    const float NEGINF = __int_as_float(0xff800000);

    // pass 1: segment max (lanes parallel over edges)
    float mx = NEGINF;
    for (int j = beg + lane; j < end; j += 32)
        mx = fmaxf(mx, lrelu(__ldg(g_asrc2 + g_csr_src[j]) + adv));
#pragma unroll
    for (int o = 16; o; o >>= 1)
        mx = fmaxf(mx, __shfl_xor_sync(0xffffffffu, mx, o));

    // pass 2: segment sum of exp
    float sm = 0.f;
    for (int j = beg + lane; j < end; j += 32)
        sm += expf(lrelu(__ldg(g_asrc2 + g_csr_src[j]) + adv) - mx);
#pragma unroll
    for (int o = 16; o; o >>= 1)
        sm += __shfl_xor_sync(0xffffffffu, sm, o);
    float inv = 1.f / (sm + 1e-16f);

    // pass 3: weighted gather of H2 rows (serial over edges, lanes = channels)
    float acc = 0.f;
    for (int j = beg; j < end; j++) {
        int s = g_csr_src[j];                       // broadcast load
        float al = expf(lrelu(__ldg(g_asrc2 + s) + adv) - mx) * inv;
        if (lane < 30) acc = fmaf(al, __ldg(g_H2 + (size_t)s * 30 + lane), acc);
    }
    if (lane < 30) out[(size_t)d * 30 + lane] = acc + __ldg(b2 + lane);
}

// ---------------------------------------------------------------------------
// launch
// ---------------------------------------------------------------------------
extern "C" void kernel_launch(void* const* d_in, const int* in_sizes, int n_in,
                              void* d_out, int out_size) {
    const float* x       = (const float*)d_in[0];
    const int*   ei      = (const int*)d_in[1];
    const float* W1      = (const float*)d_in[2];
    const float* attsrc1 = (const float*)d_in[3];
    const float* attdst1 = (const float*)d_in[4];
    // d_in[5] = b1: BN-invariant, skipped
    const float* gamma   = (const float*)d_in[6];
    const float* beta    = (const float*)d_in[7];
    const float* W2      = (const float*)d_in[8];
    const float* attsrc2 = (const float*)d_in[9];
    const float* attdst2 = (const float*)d_in[10];
    const float* b2      = (const float*)d_in[11];
    float* out = (float*)d_out;

    int Nn = in_sizes[0] / 2000;
    int E  = in_sizes[1] / 2;
    int Etot = E + Nn;
    int eb = (Etot + 255) / 256;

    cudaFuncSetAttribute(k_gemm1h, cudaFuncAttributeMaxDynamicSharedMemorySize, SMEM_GEMM);

    k_init<<<256, 256>>>(Nn);
    k_cvtA<<<2048, 256>>>(x, (size_t)Nn * 2000 / 8);
    k_cvtBT<<<dim3(64, 63), dim3(32, 8)>>>(W1);
    k_deg<<<eb, 256>>>(ei, E, Nn);
    k_scan<<<1, 1024>>>(Nn);
    k_scatter<<<eb, 256>>>(ei, E, Nn);

    dim3 g1(16, (Nn + 127) / 128);   // x = col tiles (share A rows in L2)
    k_gemm1h<<<g1, 256, SMEM_GEMM>>>(Nn);

    k_att1<<<(Nn * 4 * 32 + 255) / 256, 256>>>(attsrc1, attdst1, Nn);

    k_agg1<<<Nn, 256>>>(Nn);

    dim3 gs(2, (Nn + 63) / 64);
    k_bnstats<<<gs, 256>>>(Nn);

    k_l2prep<<<(int)(((size_t)Nn * 32 + 255) / 256), 256>>>(
        W2, attsrc2, attdst2, gamma, beta, Nn, 1.f / (float)Nn);

    k_l2agg<<<(int)(((size_t)Nn * 32 + 255) / 256), 256>>>(b2, out, Nn);
}

// round 15
// speedup vs baseline: 1.6172x; 1.0359x over previous
#include <cuda_runtime.h>
#include <cuda_fp16.h>
#include <cstdint>
#include <cstddef>

// ---------------------------------------------------------------------------
// GATEncoder: GATConv(2000->4x512, mean heads) -> BN -> ELU -> GATConv(512->30)
// N=50000, F=2000, H=4, C=512, LAT=30, E=800000 (+N self loops)
// R15: att1 fused into GEMM1 epilogue (register-resident partial dots +
//      spread atomics; k_att1 deleted) + CSR build branch overlapped with the
//      cvt/GEMM branch via stream fork/join inside graph capture.
//      Everything else identical to the 2575us R14.
// ---------------------------------------------------------------------------

#define NMAX 50000
#define EMAX 800000
#define ETMAX (EMAX + NMAX)

#define GEMM_STAGES 4
#define ROW_BYTES 80                       // 32 halfs (64B) + 16B pad: LDSM conflict-free
#define OP_TILE (128 * ROW_BYTES)          // 10240 B per operand per stage
#define STAGE_BYTES (2 * OP_TILE)          // 20480
#define SMEM_GEMM (GEMM_STAGES * STAGE_BYTES)   // 81920

// ---- device scratch (static; no runtime allocation allowed) ----
__device__ __half   g_H1h[(size_t)NMAX * 2048];   // x @ W1 in fp16
__device__ __half   g_Ah[(size_t)NMAX * 2000];    // x in fp16
__device__ __half   g_W1h[(size_t)2048 * 2000];   // W1^T in fp16 ([n][k])
__device__ float    g_out1[(size_t)NMAX * 512];   // layer-1 aggregate
__device__ float    g_H2[(size_t)NMAX * 30];      // ELU(BN(out1)) @ W2
__device__ float    g_asrc1[NMAX * 4];
__device__ float    g_adst1[NMAX * 4];
__device__ float    g_asrc2[NMAX];
__device__ float    g_adst2[NMAX];
__device__ float    g_stats[1024];                // [0:512) sum, [512:1024) sumsq
// CSR by destination
__device__ int      g_deg[NMAX];
__device__ int      g_rowptr[NMAX + 1];
__device__ int      g_woff[NMAX];
__device__ int      g_csr_src[ETMAX];

// ---- helpers ----
__device__ __forceinline__ uint32_t h2u(__half2 h) {
    __half2_raw r = *reinterpret_cast<__half2_raw*>(&h);
    return (uint32_t)r.x | ((uint32_t)r.y << 16);
}
__device__ __forceinline__ float2 u2f2(uint32_t u) {
    __half2_raw r; r.x = (unsigned short)(u & 0xFFFFu); r.y = (unsigned short)(u >> 16);
    __half2 h = *reinterpret_cast<__half2*>(&r);
    return __half22float2(h);
}
__device__ __forceinline__ float lrelu(float v) { return v > 0.f ? v : 0.2f * v; }

__device__ __forceinline__ void cp16(uint32_t saddr, const void* gptr, bool pred) {
    int sz = pred ? 16 : 0;   // sz=0 -> 16 bytes zero-filled (src-size form)
    asm volatile("cp.async.cg.shared.global [%0], [%1], 16, %2;\n"
                 :: "r"(saddr), "l"(gptr), "r"(sz));
}
__device__ __forceinline__ void cp_commit() {
    asm volatile("cp.async.commit_group;\n" ::: "memory");
}
__device__ __forceinline__ void cp_waitg() {
    asm volatile("cp.async.wait_group %0;\n" :: "n"(GEMM_STAGES - 2) : "memory");
}
__device__ __forceinline__ void ldsm4(uint32_t* r, uint32_t addr) {
    asm volatile("ldmatrix.sync.aligned.m8n8.x4.shared.b16 {%0,%1,%2,%3}, [%4];"
                 : "=r"(r[0]), "=r"(r[1]), "=r"(r[2]), "=r"(r[3]) : "r"(addr));
}

// ---------------------------------------------------------------------------
// init: zero CSR degree + BN stats + attention partial-dot accumulators
// ---------------------------------------------------------------------------
__global__ void k_init(int Nn) {
    int total = Nn * 4;
    for (int i = blockIdx.x * blockDim.x + threadIdx.x; i < total;
         i += gridDim.x * blockDim.x) {
        g_asrc1[i] = 0.f;
        g_adst1[i] = 0.f;
        if (i < Nn) g_deg[i] = 0;
        if (i < 1024) g_stats[i] = 0.f;
    }
}

// ---------------------------------------------------------------------------
// conversions: x -> fp16 ; W1 -> fp16 transposed [n][k]
// ---------------------------------------------------------------------------
__global__ void k_cvtA(const float* __restrict__ x, size_t n8) {
    const float4* src = (const float4*)x;
    uint4* dst = (uint4*)g_Ah;
    for (size_t i = (size_t)blockIdx.x * blockDim.x + threadIdx.x; i < n8;
         i += (size_t)gridDim.x * blockDim.x) {
        float4 v0 = __ldg(src + 2 * i);
        float4 v1 = __ldg(src + 2 * i + 1);
        uint4 o;
        o.x = h2u(__floats2half2_rn(v0.x, v0.y));
        o.y = h2u(__floats2half2_rn(v0.z, v0.w));
        o.z = h2u(__floats2half2_rn(v1.x, v1.y));
        o.w = h2u(__floats2half2_rn(v1.z, v1.w));
        dst[i] = o;
    }
}

__global__ void k_cvtBT(const float* __restrict__ W1) {
    __shared__ float t[32][33];
    int n0 = blockIdx.x * 32, k0 = blockIdx.y * 32;
    int tx = threadIdx.x, ty = threadIdx.y;   // 32 x 8
#pragma unroll
    for (int i = 0; i < 32; i += 8) {
        int k = k0 + ty + i;
        t[ty + i][tx] = (k < 2000) ? W1[(size_t)k * 2048 + n0 + tx] : 0.f;
    }
    __syncthreads();
#pragma unroll
    for (int i = 0; i < 32; i += 8) {
        int k = k0 + tx;
        if (k < 2000)
            g_W1h[(size_t)(n0 + ty + i) * 2000 + k] = __float2half_rn(t[tx][ty + i]);
    }
}

// ---------------------------------------------------------------------------
// CSR build: degree count -> exclusive scan -> scatter (src indices)
// ---------------------------------------------------------------------------
__global__ void k_deg(const int* __restrict__ ei, int E, int Nn) {
    int e = blockIdx.x * blockDim.x + threadIdx.x;
    if (e >= E + Nn) return;
    int d = (e < E) ? ei[E + e] : e - E;
    atomicAdd(&g_deg[d], 1);
}

__global__ void k_scan(int Nn) {
    __shared__ int wsum[32];
    __shared__ int carry_s;
    int tid = threadIdx.x;
    if (tid == 0) carry_s = 0;
    __syncthreads();
    int iters = (Nn + 1023) / 1024;
    for (int it = 0; it < iters; it++) {
        int i = it * 1024 + tid;
        int v = (i < Nn) ? g_deg[i] : 0;
        int x = v;
#pragma unroll
        for (int o = 1; o < 32; o <<= 1) {
            int y = __shfl_up_sync(0xffffffffu, x, o);
            if ((tid & 31) >= o) x += y;
        }
        if ((tid & 31) == 31) wsum[tid >> 5] = x;
        __syncthreads();
        if (tid < 32) {
            int w = wsum[tid];
#pragma unroll
            for (int o = 1; o < 32; o <<= 1) {
                int y = __shfl_up_sync(0xffffffffu, w, o);
                if (tid >= o) w += y;
            }
            wsum[tid] = w;
        }
        __syncthreads();
        int warp = tid >> 5;
        int incl = x + (warp ? wsum[warp - 1] : 0);
        int excl = incl - v;
        int c = carry_s;
        if (i < Nn) { g_rowptr[i] = c + excl; g_woff[i] = c + excl; }
        __syncthreads();
        if (tid == 1023) carry_s = c + incl;
        __syncthreads();
    }
    if (tid == 0) g_rowptr[Nn] = carry_s;
}

__global__ void k_scatter(const int* __restrict__ ei, int E, int Nn) {
    int e = blockIdx.x * blockDim.x + threadIdx.x;
    if (e >= E + Nn) return;
    int s, d;
    if (e < E) { s = ei[e]; d = ei[E + e]; } else { s = d = e - E; }
    int pos = atomicAdd(&g_woff[d], 1);
    g_csr_src[pos] = s;
}

// ---------------------------------------------------------------------------
// GEMM1 + fused attention dots: g_H1h = Ah @ W1h^T (fp16 mma, f32 accum,
// fp16 out). Epilogue also computes per-(row,head) partial dots with
// att_src/att_dst from register accumulators -> spread atomicAdd.
// ---------------------------------------------------------------------------
__global__ __launch_bounds__(256, 2)
void k_gemm1h(const float* __restrict__ att_src, const float* __restrict__ att_dst,
              int M) {
    extern __shared__ char smem[];
    const uint32_t sb = (uint32_t)__cvta_generic_to_shared(smem);
    const __half* A = g_Ah;
    const __half* B = g_W1h;

    const int tid  = threadIdx.x;
    const int lane = tid & 31, warp = tid >> 5;
    const int gid  = lane >> 2, tig = lane & 3;
    const int wm   = warp >> 1, wn = warp & 1;
    const int rowBase = blockIdx.y * 128;
    const int colBase = blockIdx.x * 128;
    const int KITERS = 63;   // ceil(2000/32); tail chunks zero-filled by cp.async

    const int mrow = (lane & 7) + ((lane >> 3) & 1) * 8;
    const int koff = ((lane >> 4) & 1) * 16;

    float acc[2][8][4];
#pragma unroll
    for (int i = 0; i < 2; i++)
#pragma unroll
        for (int j = 0; j < 8; j++)
#pragma unroll
            for (int k = 0; k < 4; k++) acc[i][j][k] = 0.f;

    auto load_tile = [&](int st, int k0) {
        uint32_t aBase = sb + st * STAGE_BYTES;
        uint32_t bBase = aBase + OP_TILE;
#pragma unroll
        for (int i = 0; i < 2; i++) {
            int idx = tid + i * 256;
            int r = idx >> 2, j = idx & 3;
            int gr = rowBase + r;
            bool p = (gr < M) && (k0 + j * 8 < 2000);
            cp16(aBase + r * ROW_BYTES + j * 16, A + (size_t)gr * 2000 + k0 + j * 8, p);
        }
#pragma unroll
        for (int i = 0; i < 2; i++) {
            int idx = tid + i * 256;
            int r = idx >> 2, j = idx & 3;
            bool p = (k0 + j * 8 < 2000);
            cp16(bBase + r * ROW_BYTES + j * 16,
                 B + (size_t)(colBase + r) * 2000 + k0 + j * 8, p);
        }
    };

#pragma unroll
    for (int s = 0; s < GEMM_STAGES - 1; s++) {
        load_tile(s, s * 32);
        cp_commit();
    }

    for (int it = 0; it < KITERS; it++) {
        cp_waitg();
        __syncthreads();
        int st = it & (GEMM_STAGES - 1);
        uint32_t aBase = sb + st * STAGE_BYTES;
        uint32_t bBase = aBase + OP_TILE;
#pragma unroll
        for (int ks = 0; ks < 2; ks++) {
            uint32_t a[2][4], bf[4][4];
#pragma unroll
            for (int tm = 0; tm < 2; tm++) {
                uint32_t addr = aBase + (wm * 32 + tm * 16 + mrow) * ROW_BYTES
                              + ks * 32 + koff;
                ldsm4(a[tm], addr);
            }
#pragma unroll
            for (int tp = 0; tp < 4; tp++) {
                uint32_t addr = bBase + (wn * 64 + tp * 16 + mrow) * ROW_BYTES
                              + ks * 32 + koff;
                ldsm4(bf[tp], addr);
            }
#pragma unroll
            for (int tm = 0; tm < 2; tm++)
#pragma unroll
                for (int tp = 0; tp < 4; tp++) {
                    asm volatile(
                        "mma.sync.aligned.m16n8k16.row.col.f32.f16.f16.f32 "
                        "{%0,%1,%2,%3},{%4,%5,%6,%7},{%8,%9},{%0,%1,%2,%3};\n"
                        : "+f"(acc[tm][tp * 2][0]), "+f"(acc[tm][tp * 2][1]),
                          "+f"(acc[tm][tp * 2][2]), "+f"(acc[tm][tp * 2][3])
                        : "r"(a[tm][0]), "r"(a[tm][1]), "r"(a[tm][2]), "r"(a[tm][3]),
                          "r"(bf[tp][0]), "r"(bf[tp][2]));
                    asm volatile(
                        "mma.sync.aligned.m16n8k16.row.col.f32.f16.f16.f32 "
                        "{%0,%1,%2,%3},{%4,%5,%6,%7},{%8,%9},{%0,%1,%2,%3};\n"
                        : "+f"(acc[tm][tp * 2 + 1][0]), "+f"(acc[tm][tp * 2 + 1][1]),
                          "+f"(acc[tm][tp * 2 + 1][2]), "+f"(acc[tm][tp * 2 + 1][3])
                        : "r"(a[tm][0]), "r"(a[tm][1]), "r"(a[tm][2]), "r"(a[tm][3]),
                          "r"(bf[tp][1]), "r"(bf[tp][3]));
                }
        }
        int nit = it + GEMM_STAGES - 1;
        if (nit < KITERS) load_tile(nit & (GEMM_STAGES - 1), nit * 32);
        cp_commit();
    }

    // ---- epilogue: fp16 H1 store + fused attention partial dots ----
    const int hIdx = colBase >> 9;                      // single head per CTA
    const int cgBase = (colBase & 511) + wn * 64 + tig * 2;
    const float* asv = att_src + hIdx * 512;
    const float* adv = att_dst + hIdx * 512;

    float psrc[4] = {0.f, 0.f, 0.f, 0.f};               // [tm*2 + half]
    float pdst[4] = {0.f, 0.f, 0.f, 0.f};

#pragma unroll
    for (int tm = 0; tm < 2; tm++) {
        int r0 = rowBase + wm * 32 + tm * 16 + gid;
#pragma unroll
        for (int tn = 0; tn < 8; tn++) {
            int c = colBase + wn * 64 + tn * 8 + tig * 2;
            uint32_t p01 = h2u(__floats2half2_rn(acc[tm][tn][0], acc[tm][tn][1]));
            uint32_t p23 = h2u(__floats2half2_rn(acc[tm][tn][2], acc[tm][tn][3]));
            if (r0 < M)
                *(uint32_t*)(g_H1h + (size_t)r0 * 2048 + c) = p01;
            if (r0 + 8 < M)
                *(uint32_t*)(g_H1h + (size_t)(r0 + 8) * 2048 + c) = p23;

            float2 av = __ldg((const float2*)(asv + cgBase + tn * 8));
            float2 dv = __ldg((const float2*)(adv + cgBase + tn * 8));
            psrc[tm * 2 + 0] += acc[tm][tn][0] * av.x + acc[tm][tn][1] * av.y;
            psrc[tm * 2 + 1] += acc[tm][tn][2] * av.x + acc[tm][tn][3] * av.y;
            pdst[tm * 2 + 0] += acc[tm][tn][0] * dv.x + acc[tm][tn][1] * dv.y;
            pdst[tm * 2 + 1] += acc[tm][tn][2] * dv.x + acc[tm][tn][3] * dv.y;
        }
    }
#pragma unroll
    for (int tm = 0; tm < 2; tm++)
#pragma unroll
        for (int half = 0; half < 2; half++) {
            int row = rowBase + wm * 32 + tm * 16 + half * 8 + gid;
            if (row < M) {
                atomicAdd(g_asrc1 + row * 4 + hIdx, psrc[tm * 2 + half]);
                atomicAdd(g_adst1 + row * 4 + hIdx, pdst[tm * 2 + half]);
            }
        }
}

// ---------------------------------------------------------------------------
// fused layer-1 softmax + aggregation: one block (256 thr) per destination.
// ---------------------------------------------------------------------------
__global__ __launch_bounds__(256)
void k_agg1(int Nn) {
    const int d = blockIdx.x;
    const int tid = threadIdx.x, lane = tid & 31, warp = tid >> 5;
    const int beg = g_rowptr[d], end = g_rowptr[d + 1];

    __shared__ float4 rwarp[8];
    __shared__ float4 rbc;
    __shared__ int    ssrc[256];
    __shared__ float4 sal[256];

    float4 ad = *(const float4*)(g_adst1 + (size_t)d * 4);
    const float NEGINF = __int_as_float(0xff800000);

    float4 mx = make_float4(NEGINF, NEGINF, NEGINF, NEGINF);
    for (int j = beg + tid; j < end; j += 256) {
        int s = g_csr_src[j];
        float4 as = *(const float4*)(g_asrc1 + (size_t)s * 4);
        mx.x = fmaxf(mx.x, lrelu(as.x + ad.x));
        mx.y = fmaxf(mx.y, lrelu(as.y + ad.y));
        mx.z = fmaxf(mx.z, lrelu(as.z + ad.z));
        mx.w = fmaxf(mx.w, lrelu(as.w + ad.w));
    }
#pragma unroll
    for (int o = 16; o; o >>= 1) {
        mx.x = fmaxf(mx.x, __shfl_down_sync(0xffffffffu, mx.x, o));
        mx.y = fmaxf(mx.y, __shfl_down_sync(0xffffffffu, mx.y, o));
        mx.z = fmaxf(mx.z, __shfl_down_sync(0xffffffffu, mx.z, o));
        mx.w = fmaxf(mx.w, __shfl_down_sync(0xffffffffu, mx.w, o));
    }
    if (lane == 0) rwarp[warp] = mx;
    __syncthreads();
    if (tid == 0) {
        float4 m = rwarp[0];
#pragma unroll
        for (int w = 1; w < 8; w++) {
            m.x = fmaxf(m.x, rwarp[w].x); m.y = fmaxf(m.y, rwarp[w].y);
            m.z = fmaxf(m.z, rwarp[w].z); m.w = fmaxf(m.w, rwarp[w].w);
        }
        rbc = m;
    }
    __syncthreads();
    mx = rbc;

    float4 sm = make_float4(0.f, 0.f, 0.f, 0.f);
    for (int j = beg + tid; j < end; j += 256) {
        int s = g_csr_src[j];
        float4 as = *(const float4*)(g_asrc1 + (size_t)s * 4);
        sm.x += expf(lrelu(as.x + ad.x) - mx.x);
        sm.y += expf(lrelu(as.y + ad.y) - mx.y);
        sm.z += expf(lrelu(as.z + ad.z) - mx.z);
        sm.w += expf(lrelu(as.w + ad.w) - mx.w);
    }
#pragma unroll
    for (int o = 16; o; o >>= 1) {
        sm.x += __shfl_down_sync(0xffffffffu, sm.x, o);
        sm.y += __shfl_down_sync(0xffffffffu, sm.y, o);
        sm.z += __shfl_down_sync(0xffffffffu, sm.z, o);
        sm.w += __shfl_down_sync(0xffffffffu, sm.w, o);
    }
    if (lane == 0) rwarp[warp] = sm;
    __syncthreads();
    if (tid == 0) {
        float4 t = rwarp[0];
#pragma unroll
        for (int w = 1; w < 8; w++) {
            t.x += rwarp[w].x; t.y += rwarp[w].y; t.z += rwarp[w].z; t.w += rwarp[w].w;
        }
        rbc = t;
    }
    __syncthreads();
    sm = rbc;
    float4 inv;
    inv.x = 0.25f / (sm.x + 1e-16f);
    inv.y = 0.25f / (sm.y + 1e-16f);
    inv.z = 0.25f / (sm.z + 1e-16f);
    inv.w = 0.25f / (sm.w + 1e-16f);

    float2 acc = make_float2(0.f, 0.f);
    for (int c0 = beg; c0 < end; c0 += 256) {
        int cnt = min(end - c0, 256);
        __syncthreads();
        if (tid < cnt) {
            int s = g_csr_src[c0 + tid];
            float4 as = *(const float4*)(g_asrc1 + (size_t)s * 4);
            float4 al;
            al.x = expf(lrelu(as.x + ad.x) - mx.x) * inv.x;
            al.y = expf(lrelu(as.y + ad.y) - mx.y) * inv.y;
            al.z = expf(lrelu(as.z + ad.z) - mx.z) * inv.z;
            al.w = expf(lrelu(as.w + ad.w) - mx.w) * inv.w;
            ssrc[tid] = s;
            sal[tid] = al;
        }
        __syncthreads();
        for (int jj = 0; jj < cnt; jj++) {
            const __half* h = g_H1h + (size_t)ssrc[jj] * 2048 + 2 * tid;
            float4 al = sal[jj];
            float2 v0 = u2f2(__ldg((const uint32_t*)(h)));
            float2 v1 = u2f2(__ldg((const uint32_t*)(h + 512)));
            float2 v2 = u2f2(__ldg((const uint32_t*)(h + 1024)));
            float2 v3 = u2f2(__ldg((const uint32_t*)(h + 1536)));
            acc.x += al.x * v0.x + al.y * v1.x + al.z * v2.x + al.w * v3.x;
            acc.y += al.x * v0.y + al.y * v1.y + al.z * v2.y + al.w * v3.y;
        }
    }
    *(float2*)(g_out1 + (size_t)d * 512 + 2 * tid) = acc;
}

// ---------------------------------------------------------------------------
// BatchNorm stats (b1 BN-invariant -> skipped)
// ---------------------------------------------------------------------------
__global__ void k_bnstats(int Nn) {
    int c = blockIdx.x * blockDim.x + threadIdx.x;   // 0..511
    int r0 = blockIdx.y * 64;
    int r1 = min(r0 + 64, Nn);
    float s1 = 0.f, s2 = 0.f;
    for (int r = r0; r < r1; r++) {
        float v = g_out1[(size_t)r * 512 + c];
        s1 += v;
        s2 = fmaf(v, v, s2);
    }
    atomicAdd(&g_stats[c], s1);
    atomicAdd(&g_stats[512 + c], s2);
}

// ---------------------------------------------------------------------------
// layer-2 prep with fused BN+ELU: H2 = ELU(BN(out1)) @ W2 (one warp per row)
// ---------------------------------------------------------------------------
__global__ void k_l2prep(const float* __restrict__ W2, const float* __restrict__ as2,
                         const float* __restrict__ ad2, const float* __restrict__ gamma,
                         const float* __restrict__ beta, int Nn, float invN) {
    int gw = (int)(((size_t)blockIdx.x * blockDim.x + threadIdx.x) >> 5);
    int lane = threadIdx.x & 31;
    if (gw >= Nn) return;
    const float* h = g_out1 + (size_t)gw * 512;
    float acc = 0.f;
    for (int kb = 0; kb < 16; kb++) {
        int c = kb * 32 + lane;
        float mu = __ldg(g_stats + c) * invN;
        float var = __ldg(g_stats + 512 + c) * invN - mu * mu;
        float scale = rsqrtf(var + 1e-5f) * __ldg(gamma + c);
        float shift = __ldg(beta + c) - mu * scale;
        float xv = h[c] * scale + shift;
        float hv = xv > 0.f ? xv : expm1f(xv);
#pragma unroll
        for (int j = 0; j < 32; j++) {
            float hk = __shfl_sync(0xffffffffu, hv, j);
            float w = (lane < 30) ? __ldg(W2 + (size_t)(kb * 32 + j) * 30 + lane) : 0.f;
            acc = fmaf(hk, w, acc);
        }
    }
    float sa = (lane < 30) ? acc * __ldg(as2 + lane) : 0.f;
    float sd = (lane < 30) ? acc * __ldg(ad2 + lane) : 0.f;
#pragma unroll
    for (int off = 16; off; off >>= 1) {
        sa += __shfl_down_sync(0xffffffffu, sa, off);
        sd += __shfl_down_sync(0xffffffffu, sd, off);
    }
    if (lane < 30) g_H2[(size_t)gw * 30 + lane] = acc;
    if (lane == 0) { g_asrc2[gw] = sa; g_adst2[gw] = sd; }
}

// ---------------------------------------------------------------------------
// fused layer-2 softmax + aggregation: one warp per destination.
// ---------------------------------------------------------------------------
__global__ __launch_bounds__(256)
void k_l2agg(const float* __restrict__ b2, float* __restrict__ out, int Nn) {
    int gw = (int)(((size_t)blockIdx.x * blockDim.x + threadIdx.x) >> 5);
    int lane = threadIdx.x & 31;
    if (gw >= Nn) return;
    const int d = gw;
    const int beg = g_rowptr[d], end = g_rowptr[d + 1];
    const float adv = g_adst2[d];
    const float NEGINF = __int_as_float(0xff800000);

    float mx = NEGINF;
    for (int j = beg + lane; j < end; j += 32)
        mx = fmaxf(mx, lrelu(__ldg(g_asrc2 + g_csr_src[j]) + adv));
#pragma unroll
    for (int o = 16; o; o >>= 1)
        mx = fmaxf(mx, __shfl_xor_sync(0xffffffffu, mx, o));

    float sm = 0.f;
    for (int j = beg + lane; j < end; j += 32)
        sm += expf(lrelu(__ldg(g_asrc2 + g_csr_src[j]) + adv) - mx);
#pragma unroll
    for (int o = 16; o; o >>= 1)
        sm += __shfl_xor_sync(0xffffffffu, sm, o);
    float inv = 1.f / (sm + 1e-16f);

    float acc = 0.f;
    for (int j = beg; j < end; j++) {
        int s = g_csr_src[j];
        float al = expf(lrelu(__ldg(g_asrc2 + s) + adv) - mx) * inv;
        if (lane < 30) acc = fmaf(al, __ldg(g_H2 + (size_t)s * 30 + lane), acc);
    }
    if (lane < 30) out[(size_t)d * 30 + lane] = acc + __ldg(b2 + lane);
}

// ---------------------------------------------------------------------------
// launch: fork CSR branch (deg/scan/scatter) parallel to cvt+GEMM branch
// ---------------------------------------------------------------------------
extern "C" void kernel_launch(void* const* d_in, const int* in_sizes, int n_in,
                              void* d_out, int out_size) {
    const float* x       = (const float*)d_in[0];
    const int*   ei      = (const int*)d_in[1];
    const float* W1      = (const float*)d_in[2];
    const float* attsrc1 = (const float*)d_in[3];
    const float* attdst1 = (const float*)d_in[4];
    // d_in[5] = b1: BN-invariant, skipped
    const float* gamma   = (const float*)d_in[6];
    const float* beta    = (const float*)d_in[7];
    const float* W2      = (const float*)d_in[8];
    const float* attsrc2 = (const float*)d_in[9];
    const float* attdst2 = (const float*)d_in[10];
    const float* b2      = (const float*)d_in[11];
    float* out = (float*)d_out;

    int Nn = in_sizes[0] / 2000;
    int E  = in_sizes[1] / 2;
    int Etot = E + Nn;
    int eb = (Etot + 255) / 256;

    cudaFuncSetAttribute(k_gemm1h, cudaFuncAttributeMaxDynamicSharedMemorySize, SMEM_GEMM);

    cudaStream_t s2;
    cudaEvent_t evFork, evJoin;
    cudaStreamCreateWithFlags(&s2, cudaStreamNonBlocking);
    cudaEventCreateWithFlags(&evFork, cudaEventDisableTiming);
    cudaEventCreateWithFlags(&evJoin, cudaEventDisableTiming);

    k_init<<<512, 256>>>(Nn);

    // fork: CSR branch on s2
    cudaEventRecord(evFork, 0);
    cudaStreamWaitEvent(s2, evFork, 0);
    k_deg<<<eb, 256, 0, s2>>>(ei, E, Nn);
    k_scan<<<1, 1024, 0, s2>>>(Nn);
    k_scatter<<<eb, 256, 0, s2>>>(ei, E, Nn);
    cudaEventRecord(evJoin, s2);

    // main branch: conversions + GEMM(+att dots)
    k_cvtA<<<2048, 256>>>(x, (size_t)Nn * 2000 / 8);
    k_cvtBT<<<dim3(64, 63), dim3(32, 8)>>>(W1);
    dim3 g1(16, (Nn + 127) / 128);
    k_gemm1h<<<g1, 256, SMEM_GEMM>>>(attsrc1, attdst1, Nn);

    // join: agg1 needs CSR + attention scalars
    cudaStreamWaitEvent(0, evJoin, 0);
    k_agg1<<<Nn, 256>>>(Nn);

    dim3 gs(2, (Nn + 63) / 64);
    k_bnstats<<<gs, 256>>>(Nn);

    k_l2prep<<<(int)(((size_t)Nn * 32 + 255) / 256), 256>>>(
        W2, attsrc2, attdst2, gamma, beta, Nn, 1.f / (float)Nn);

    k_l2agg<<<(int)(((size_t)Nn * 32 + 255) / 256), 256>>>(b2, out, Nn);
}